// round 1
// baseline (speedup 1.0000x reference)
#include <cuda_runtime.h>

// ---------------------------------------------------------------------------
// Problem constants
// ---------------------------------------------------------------------------
#define NMAX   65536
#define MNBR   12
#define ATOMF  64
#define INF_   192
#define BD     192     // k_main block size
#define APB    32      // atoms per block in k_main

// ---------------------------------------------------------------------------
// Device scratch (static — no allocations allowed)
// ---------------------------------------------------------------------------
__device__ float g_Pself[NMAX * INF_];            // 48 MB : [WK|WQ|WV] self-cols @ atom[n]
__device__ float g_Pnbr [NMAX * INF_];            // 48 MB : [WK|WQ|WV] nbr-cols  @ atom[n]
__device__ float g_gated[(size_t)NMAX * MNBR * 128]; // 384 MB pre-BN gated
__device__ float g_s    [NMAX * ATOMF];           // 16 MB nbr_sumed pre-BN2
__device__ float g_Wfu  [128 * 64];               // fused W_fc @ WO
__device__ float g_sum1[128], g_sq1[128], g_sum2[64], g_sq2[64];
__device__ float g_sc1[128], g_sh1[128], g_sc2[64], g_sh2[64];

// ---------------------------------------------------------------------------
// Packed f32x2 FMA helpers (sm_100+ only; ptxas never emits these from C++)
// ---------------------------------------------------------------------------
__device__ __forceinline__ void fma2(unsigned long long &d,
                                     unsigned long long a,
                                     unsigned long long b) {
    asm("fma.rn.f32x2 %0, %1, %2, %0;" : "+l"(d) : "l"(a), "l"(b));
}
__device__ __forceinline__ float2 upk(unsigned long long v) {
    float2 r;
    asm("mov.b64 {%0,%1}, %2;" : "=f"(r.x), "=f"(r.y) : "l"(v));
    return r;
}

__device__ __forceinline__ float sigf(float x) { return 1.f / (1.f + __expf(-x)); }
__device__ __forceinline__ float spf (float x) { return fmaxf(x, 0.f) + log1pf(__expf(-fabsf(x))); }

// ---------------------------------------------------------------------------
// K_wfuse: Wfu[g][a] = sum_o W_fc[g][o] * WO[o][a]  (+ zero BN stat accumulators)
// grid 32 x 256
// ---------------------------------------------------------------------------
__global__ void k_wfuse(const float* __restrict__ Wfc, const float* __restrict__ WO) {
    int t = threadIdx.x;
    if (blockIdx.x == 0) {
        if (t < 128) { g_sum1[t] = 0.f; g_sq1[t] = 0.f; }
        if (t < 64)  { g_sum2[t] = 0.f; g_sq2[t] = 0.f; }
    }
    int o = blockIdx.x * 256 + t;        // 8192 outputs
    int g = o >> 6, a = o & 63;
    const float* wr = Wfc + g * 256;
    float acc = 0.f;
    #pragma unroll 8
    for (int q = 0; q < 256; q++) acc += wr[q] * WO[q * 64 + a];
    g_Wfu[o] = acc;
}

// ---------------------------------------------------------------------------
// K_proj: per-atom projections through self / neighbor weight column blocks.
//   Pself[n][p*64+a] = sum_f atom[n][f] * Wp[a][f]        (cols 0..63)
//   Pnbr [n][p*64+a] = sum_f atom[n][f] * Wp[a][64+f]     (cols 64..127)
// 384 threads: t<192 -> Pself row j=t ; t>=192 -> Pnbr row j=t-192.
// Weight row held in registers (64 floats), reused across 64 atoms/block.
// ---------------------------------------------------------------------------
__global__ __launch_bounds__(384) void k_proj(const float* __restrict__ atom,
                                              const float* __restrict__ WK,
                                              const float* __restrict__ WQ,
                                              const float* __restrict__ WV,
                                              int N) {
    __shared__ __align__(16) float at[16 * 68];
    int tid  = threadIdx.x;
    int half = (tid >= 192);
    int j    = half ? tid - 192 : tid;
    int proj = j >> 6, a = j & 63;
    const float* W  = (proj == 0) ? WK : ((proj == 1) ? WQ : WV);
    const float* wr = W + a * INF_ + (half ? 64 : 0);

    unsigned long long w2[32];
    #pragma unroll
    for (int f2 = 0; f2 < 32; f2++)
        w2[f2] = *(const unsigned long long*)(wr + 2 * f2);

    float* ob = half ? g_Pnbr : g_Pself;

    for (int t16 = 0; t16 < 4; t16++) {
        int n0 = (blockIdx.x * 4 + t16) * 16;
        if (n0 >= N) break;
        __syncthreads();
        for (int e = tid; e < 1024; e += 384)
            at[(e >> 6) * 68 + (e & 63)] = atom[(size_t)(n0 + (e >> 6)) * 64 + (e & 63)];
        __syncthreads();
        #pragma unroll 2
        for (int a16 = 0; a16 < 16; a16++) {
            unsigned long long acc0 = 0ull, acc1 = 0ull;
            const float* ar = at + a16 * 68;
            #pragma unroll
            for (int f2 = 0; f2 < 32; f2 += 2) {
                fma2(acc0, w2[f2],     *(const unsigned long long*)(ar + 2 * f2));
                fma2(acc1, w2[f2 + 1], *(const unsigned long long*)(ar + 2 * f2 + 2));
            }
            float2 p0 = upk(acc0), p1 = upk(acc1);
            ob[(size_t)(n0 + a16) * INF_ + j] = p0.x + p0.y + p1.x + p1.y;
        }
    }
}

// ---------------------------------------------------------------------------
// K_main: per atom — gather + edge projection -> KQV -> attention -> fused
// gated projection; store pre-BN gated; accumulate BN1 stats.
// Dynamic smem layout (float offsets), all 16B aligned where vectorized:
// ---------------------------------------------------------------------------
#define O_WE   0                 // 192 rows x stride 68 (edge weights, cols 128..191)
#define O_WFU  13056             // 128 rows x stride 68 (fused weight)
#define O_PS   21760             // 192 (Pself of current atom)
#define O_KQV  21952             // 12 rows x stride 200  (K | Q+64 | V+128)
#define O_NF   24352             // 12 rows x stride 68   (nbr_fea tile)
#define O_ATT  25168             // 12 rows x stride 68   (attention output)
#define O_WLG  25984             // 12 x 16 (logits / softmax weights)
#define O_JIX  26176             // 12 ints
#define SMEM_FLOATS 26192
#define SMEM_MAIN_BYTES (SMEM_FLOATS * 4)

__global__ __launch_bounds__(BD, 2) void k_main(const float* __restrict__ nbr,
                                                const int*   __restrict__ idx,
                                                const float* __restrict__ WK,
                                                const float* __restrict__ WQ,
                                                const float* __restrict__ WV,
                                                const float* __restrict__ bfc,
                                                int N) {
    extern __shared__ float sm[];
    float* sWE  = sm + O_WE;
    float* sWFU = sm + O_WFU;
    float* sPS  = sm + O_PS;
    float* sKQV = sm + O_KQV;
    float* sNF  = sm + O_NF;
    float* sATT = sm + O_ATT;
    float* sWLG = sm + O_WLG;
    int*   sJ   = (int*)(sm + O_JIX);

    int tid = threadIdx.x;

    // --- stage weights into smem (once per block) ---
    for (int i = tid; i < 192 * 64; i += BD) {
        int j = i >> 6, f = i & 63;
        const float* W = (j < 64) ? WK : ((j < 128) ? WQ : WV);
        sWE[j * 68 + f] = W[(j & 63) * INF_ + 128 + f];
    }
    for (int i = tid; i < 128 * 64; i += BD)
        sWFU[(i >> 6) * 68 + (i & 63)] = g_Wfu[i];
    float bfc_r = (tid < 128) ? bfc[tid] : 0.f;

    float ssum = 0.f, ssq = 0.f;

    for (int ai = 0; ai < APB; ai++) {
        int n = blockIdx.x * APB + ai;
        if (n >= N) break;

        // ---- loads: Pself row, nbr_fea tile, neighbor indices ----
        sPS[tid] = g_Pself[(size_t)n * INF_ + tid];
        {
            const float* nb = nbr + (size_t)n * (MNBR * 64);
            #pragma unroll
            for (int s = 0; s < 4; s++) {
                int e = tid + s * BD;
                sNF[(e >> 6) * 68 + (e & 63)] = nb[e];
            }
        }
        if (tid < MNBR) sJ[tid] = idx[n * MNBR + tid];
        __syncthreads();

        // ---- gather neighbor projections + edge projection (fused) ----
        {
            float kq[MNBR];
            #pragma unroll
            for (int m = 0; m < MNBR; m++)
                kq[m] = sPS[tid] + __ldg(&g_Pnbr[(size_t)sJ[m] * INF_ + tid]);

            unsigned long long acc[MNBR];
            #pragma unroll
            for (int m = 0; m < MNBR; m++) acc[m] = 0ull;

            const float* wr = sWE + tid * 68;
            #pragma unroll
            for (int f4 = 0; f4 < 16; f4++) {
                ulonglong2 w = *(const ulonglong2*)(wr + f4 * 4);
                #pragma unroll
                for (int m = 0; m < MNBR; m++) {
                    ulonglong2 nv = *(const ulonglong2*)(sNF + m * 68 + f4 * 4);
                    fma2(acc[m], w.x, nv.x);
                    fma2(acc[m], w.y, nv.y);
                }
            }
            #pragma unroll
            for (int m = 0; m < MNBR; m++) {
                float2 p = upk(acc[m]);
                sKQV[m * 200 + tid] = kq[m] + p.x + p.y;
            }
        }
        __syncthreads();

        // ---- logits[m][k] = K[m].Q[k] / 8 ----
        if (tid < 144) {
            int m = tid / 12, k = tid - m * 12;
            const float* Km = sKQV + m * 200;
            const float* Qk = sKQV + k * 200 + 64;
            float acc = 0.f;
            #pragma unroll 8
            for (int a = 0; a < 64; a++) acc += Km[a] * Qk[a];
            sWLG[m * 16 + k] = acc * 0.125f;
        }
        __syncthreads();

        // ---- softmax over k ----
        if (tid < MNBR) {
            float mx = -1e30f;
            #pragma unroll
            for (int k = 0; k < MNBR; k++) mx = fmaxf(mx, sWLG[tid * 16 + k]);
            float s = 0.f;
            #pragma unroll
            for (int k = 0; k < MNBR; k++) {
                float e = __expf(sWLG[tid * 16 + k] - mx);
                sWLG[tid * 16 + k] = e;
                s += e;
            }
            float inv = 1.f / s;
            #pragma unroll
            for (int k = 0; k < MNBR; k++) sWLG[tid * 16 + k] *= inv;
        }
        __syncthreads();

        // ---- attn[m][a] = sum_k w[m][k] * V[k][a] ----
        #pragma unroll
        for (int s2 = 0; s2 < 4; s2++) {
            int e = tid + s2 * BD;
            int m = e >> 6, a = e & 63;
            float acc = 0.f;
            #pragma unroll
            for (int k = 0; k < MNBR; k++)
                acc += sWLG[m * 16 + k] * sKQV[k * 200 + 128 + a];
            sATT[m * 68 + a] = acc;
        }
        __syncthreads();

        // ---- gated[m][g] = attn[m] . Wfu[g] + b_fc[g]  (threads 0..127, g = tid) ----
        if (tid < 128) {
            unsigned long long acc[MNBR];
            #pragma unroll
            for (int m = 0; m < MNBR; m++) acc[m] = 0ull;
            const float* wr = sWFU + tid * 68;
            #pragma unroll
            for (int f4 = 0; f4 < 16; f4++) {
                ulonglong2 w = *(const ulonglong2*)(wr + f4 * 4);
                #pragma unroll
                for (int m = 0; m < MNBR; m++) {
                    ulonglong2 av = *(const ulonglong2*)(sATT + m * 68 + f4 * 4);
                    fma2(acc[m], w.x, av.x);
                    fma2(acc[m], w.y, av.y);
                }
            }
            float* go = g_gated + (size_t)n * (MNBR * 128) + tid;
            #pragma unroll
            for (int m = 0; m < MNBR; m++) {
                float2 p = upk(acc[m]);
                float v = p.x + p.y + bfc_r;
                go[m * 128] = v;
                ssum += v;
                ssq  += v * v;
            }
        }
        // next iteration's __syncthreads() (after loads) provides the barrier
    }

    if (tid < 128) {
        atomicAdd(&g_sum1[tid], ssum);
        atomicAdd(&g_sq1[tid],  ssq);
    }
}

// ---------------------------------------------------------------------------
// BN parameter kernels
// ---------------------------------------------------------------------------
__global__ void k_bn1(const float* __restrict__ g1, const float* __restrict__ b1, float invCnt) {
    int t = threadIdx.x;                  // 128
    float m = g_sum1[t] * invCnt;
    float v = g_sq1[t] * invCnt - m * m;
    float sc = g1[t] * rsqrtf(v + 1e-5f);
    g_sc1[t] = sc;
    g_sh1[t] = b1[t] - m * sc;
}
__global__ void k_bn2(const float* __restrict__ g2, const float* __restrict__ b2, float invCnt) {
    int t = threadIdx.x;                  // 64
    float m = g_sum2[t] * invCnt;
    float v = g_sq2[t] * invCnt - m * m;
    float sc = g2[t] * rsqrtf(v + 1e-5f);
    g_sc2[t] = sc;
    g_sh2[t] = b2[t] - m * sc;
}

// ---------------------------------------------------------------------------
// K_phase2: apply BN1 affine, sigmoid(filter)*softplus(core), sum over M;
// store s[n][c] and accumulate BN2 stats.
// ---------------------------------------------------------------------------
__global__ __launch_bounds__(256) void k_phase2(int N) {
    int tid = threadIdx.x;
    int sub = tid >> 6, c = tid & 63;
    float scf = g_sc1[c],      shf = g_sh1[c];
    float sch = g_sc1[c + 64], shh = g_sh1[c + 64];
    float ls = 0.f, lq = 0.f;
    int n4max = (N + 3) >> 2;
    for (int n4 = blockIdx.x; n4 < n4max; n4 += gridDim.x) {
        int n = n4 * 4 + sub;
        if (n < N) {
            const float* gp = g_gated + (size_t)n * (MNBR * 128);
            float acc = 0.f;
            #pragma unroll
            for (int m = 0; m < MNBR; m++) {
                float f = gp[m * 128 + c]      * scf + shf;
                float h = gp[m * 128 + 64 + c] * sch + shh;
                acc += sigf(f) * spf(h);
            }
            g_s[n * 64 + c] = acc;
            ls += acc;
            lq += acc * acc;
        }
    }
    atomicAdd(&g_sum2[c], ls);
    atomicAdd(&g_sq2[c],  lq);
}

// ---------------------------------------------------------------------------
// K_final: out = softplus(atom + BN2(s))
// ---------------------------------------------------------------------------
__global__ void k_final(const float* __restrict__ atom, float* __restrict__ out, int total) {
    int i = blockIdx.x * blockDim.x + threadIdx.x;
    if (i >= total) return;
    int c = i & 63;
    float v = atom[i] + g_s[i] * g_sc2[c] + g_sh2[c];
    out[i] = spf(v);
}

// ---------------------------------------------------------------------------
// kernel_launch
// ---------------------------------------------------------------------------
extern "C" void kernel_launch(void* const* d_in, const int* in_sizes, int n_in,
                              void* d_out, int out_size) {
    const float* atom = (const float*)d_in[0];
    const float* nbr  = (const float*)d_in[1];
    const int*   idx  = (const int*)  d_in[2];
    const float* WK   = (const float*)d_in[3];
    const float* WQ   = (const float*)d_in[4];
    const float* WV   = (const float*)d_in[5];
    const float* WO   = (const float*)d_in[6];
    const float* Wfc  = (const float*)d_in[7];
    const float* bfc  = (const float*)d_in[8];
    const float* bn1g = (const float*)d_in[9];
    const float* bn1b = (const float*)d_in[10];
    const float* bn2g = (const float*)d_in[11];
    const float* bn2b = (const float*)d_in[12];
    float* out = (float*)d_out;

    int N = in_sizes[0] / ATOMF;

    cudaFuncSetAttribute(k_main, cudaFuncAttributeMaxDynamicSharedMemorySize, SMEM_MAIN_BYTES);

    k_wfuse<<<32, 256>>>(Wfc, WO);
    k_proj<<<(N + 63) / 64, 384>>>(atom, WK, WQ, WV, N);
    k_main<<<(N + APB - 1) / APB, BD, SMEM_MAIN_BYTES>>>(nbr, idx, WK, WQ, WV, bfc, N);
    k_bn1<<<1, 128>>>(bn1g, bn1b, 1.f / (float)(N * MNBR));
    k_phase2<<<1024, 256>>>(N);
    k_bn2<<<1, 64>>>(bn2g, bn2b, 1.f / (float)N);
    k_final<<<(N * ATOMF + 255) / 256, 256>>>(atom, out, N * ATOMF);
}

// round 2
// speedup vs baseline: 1.2218x; 1.2218x over previous
#include <cuda_runtime.h>

// ---------------------------------------------------------------------------
// Problem constants
// ---------------------------------------------------------------------------
#define NMAX   65536
#define MNBR   12
#define ATOMF  64
#define INF_   192
#define BD     384     // k_main block size (12 warps)
#define APB    32      // atoms per block in k_main (8 groups of 4)

// ---------------------------------------------------------------------------
// Device scratch (static — no allocations allowed)
// ---------------------------------------------------------------------------
__device__ float g_Pself[NMAX * INF_];               // 48 MB
__device__ float g_Pnbr [NMAX * INF_];               // 48 MB
__device__ float g_gated[(size_t)NMAX * MNBR * 128]; // 384 MB pre-BN gated
__device__ float g_s    [NMAX * ATOMF];              // 16 MB
__device__ float g_WEt  [192 * 64];                  // edge weights, tf32-rounded
__device__ float g_Wfut [128 * 64];                  // fused W_fc@WO, tf32-rounded
__device__ float g_sum1[128], g_sq1[128], g_sum2[64], g_sq2[64];
__device__ float g_sc1[128], g_sh1[128], g_sc2[64], g_sh2[64];

// ---------------------------------------------------------------------------
// Helpers
// ---------------------------------------------------------------------------
__device__ __forceinline__ void fma2(unsigned long long &d,
                                     unsigned long long a,
                                     unsigned long long b) {
    asm("fma.rn.f32x2 %0, %1, %2, %0;" : "+l"(d) : "l"(a), "l"(b));
}
__device__ __forceinline__ float2 upk(unsigned long long v) {
    float2 r;
    asm("mov.b64 {%0,%1}, %2;" : "=f"(r.x), "=f"(r.y) : "l"(v));
    return r;
}
__device__ __forceinline__ float tf32r(float x) {
    unsigned u; asm("cvt.rna.tf32.f32 %0, %1;" : "=r"(u) : "f"(x));
    return __uint_as_float(u);
}
// D += A(16x8 row) * B(8x8 col), tf32 inputs (pre-rounded bit patterns)
__device__ __forceinline__ void mma8(float d[4], float a0, float a1, float a2, float a3,
                                     float b0, float b1) {
    unsigned A0 = __float_as_uint(a0), A1 = __float_as_uint(a1);
    unsigned A2 = __float_as_uint(a2), A3 = __float_as_uint(a3);
    unsigned B0 = __float_as_uint(b0), B1 = __float_as_uint(b1);
    asm volatile("mma.sync.aligned.m16n8k8.row.col.f32.tf32.tf32.f32 "
                 "{%0,%1,%2,%3}, {%4,%5,%6,%7}, {%8,%9}, {%0,%1,%2,%3};"
                 : "+f"(d[0]), "+f"(d[1]), "+f"(d[2]), "+f"(d[3])
                 : "r"(A0), "r"(A1), "r"(A2), "r"(A3), "r"(B0), "r"(B1));
}
__device__ __forceinline__ float sigf(float x) { return 1.f / (1.f + __expf(-x)); }
__device__ __forceinline__ float spf (float x) { return fmaxf(x, 0.f) + log1pf(__expf(-fabsf(x))); }

// ---------------------------------------------------------------------------
// K_prep: tf32-round edge weights; fuse W_fc@WO and tf32-round; zero stats.
// grid 80 x 256: o<12288 -> WE, else Wfu.
// ---------------------------------------------------------------------------
__global__ void k_prep(const float* __restrict__ WK, const float* __restrict__ WQ,
                       const float* __restrict__ WV, const float* __restrict__ Wfc,
                       const float* __restrict__ WO) {
    int t = threadIdx.x;
    if (blockIdx.x == 0) {
        if (t < 128) { g_sum1[t] = 0.f; g_sq1[t] = 0.f; }
        if (t < 64)  { g_sum2[t] = 0.f; g_sq2[t] = 0.f; }
    }
    int o = blockIdx.x * 256 + t;
    if (o < 12288) {
        int j = o >> 6, f = o & 63;
        const float* W = (j < 64) ? WK : ((j < 128) ? WQ : WV);
        g_WEt[o] = tf32r(W[(j & 63) * INF_ + 128 + f]);
    } else {
        int p = o - 12288;           // 8192 entries
        int g = p >> 6, a = p & 63;
        const float* wr = Wfc + g * 256;
        float acc = 0.f;
        #pragma unroll 8
        for (int q = 0; q < 256; q++) acc += wr[q] * WO[q * 64 + a];
        g_Wfut[p] = tf32r(acc);
    }
}

// ---------------------------------------------------------------------------
// K_proj: per-atom self/neighbor projections (exact f32, FFMA2 path).
// ---------------------------------------------------------------------------
__global__ __launch_bounds__(384) void k_proj(const float* __restrict__ atom,
                                              const float* __restrict__ WK,
                                              const float* __restrict__ WQ,
                                              const float* __restrict__ WV,
                                              int N) {
    __shared__ __align__(16) float at[16 * 68];
    int tid  = threadIdx.x;
    int half = (tid >= 192);
    int j    = half ? tid - 192 : tid;
    int proj = j >> 6, a = j & 63;
    const float* W  = (proj == 0) ? WK : ((proj == 1) ? WQ : WV);
    const float* wr = W + a * INF_ + (half ? 64 : 0);

    unsigned long long w2[32];
    #pragma unroll
    for (int f2 = 0; f2 < 32; f2++)
        w2[f2] = *(const unsigned long long*)(wr + 2 * f2);

    float* ob = half ? g_Pnbr : g_Pself;

    for (int t16 = 0; t16 < 4; t16++) {
        int n0 = (blockIdx.x * 4 + t16) * 16;
        if (n0 >= N) break;
        __syncthreads();
        for (int e = tid; e < 1024; e += 384)
            at[(e >> 6) * 68 + (e & 63)] = atom[(size_t)(n0 + (e >> 6)) * 64 + (e & 63)];
        __syncthreads();
        #pragma unroll 2
        for (int a16 = 0; a16 < 16; a16++) {
            unsigned long long acc0 = 0ull, acc1 = 0ull;
            const float* ar = at + a16 * 68;
            #pragma unroll
            for (int f2 = 0; f2 < 32; f2 += 2) {
                fma2(acc0, w2[f2],     *(const unsigned long long*)(ar + 2 * f2));
                fma2(acc1, w2[f2 + 1], *(const unsigned long long*)(ar + 2 * f2 + 2));
            }
            float2 p0 = upk(acc0), p1 = upk(acc1);
            ob[(size_t)(n0 + a16) * INF_ + j] = p0.x + p0.y + p1.x + p1.y;
        }
    }
}

// ---------------------------------------------------------------------------
// K_main (tensor-core version): groups of 4 atoms = 48 MMA rows.
//   edge proj : NF[48x64] @ WEt^T[64x192]  (mma tf32)  + Pself + Pnbr gather
//   attention : scalar f32 (logits, softmax, w@V)
//   gated proj: ATT[48x64] @ Wfut^T[64x128] (mma tf32) + b_fc -> g_gated, stats
// ---------------------------------------------------------------------------
#define O_WE   0                 // 192 x 68
#define O_WFU  13056             // 128 x 68
#define O_NF   21760             // 48 x 68   (tf32-rounded)
#define O_KQV  25024             // 48 x 200  (K | Q+64 | V+128), f32
#define O_ATT  34624             // 48 x 68   (tf32-rounded)
#define O_PS   37888             // 4 x 192
#define O_LG   38656             // 48 x 16
#define O_J    39424             // 48 ints
#define SMEM_FLOATS 39472
#define SMEM_MAIN_BYTES (SMEM_FLOATS * 4)

__global__ __launch_bounds__(BD, 1) void k_main(const float* __restrict__ nbr,
                                                const int*   __restrict__ idx,
                                                const float* __restrict__ bfc,
                                                int N) {
    extern __shared__ float sm[];
    float* sWE  = sm + O_WE;
    float* sWFU = sm + O_WFU;
    float* sNF  = sm + O_NF;
    float* sKQV = sm + O_KQV;
    float* sATT = sm + O_ATT;
    float* sPS  = sm + O_PS;
    float* sLG  = sm + O_LG;
    int*   sJ   = (int*)(sm + O_J);

    int tid  = threadIdx.x;
    int wid  = tid >> 5;
    int lane = tid & 31;
    int qid  = lane >> 2;   // 0..7
    int tq   = lane & 3;    // 0..3

    // stage weights (already tf32-rounded)
    for (int i = tid; i < 192 * 64; i += BD) sWE [(i >> 6) * 68 + (i & 63)] = g_WEt[i];
    for (int i = tid; i < 128 * 64; i += BD) sWFU[(i >> 6) * 68 + (i & 63)] = g_Wfut[i];

    // per-thread gated channels (warps 0..7): cols (2*wid+nti)*8 + 2*tq (+1)
    float bf_x[2] = {0.f, 0.f}, bf_y[2] = {0.f, 0.f};
    if (wid < 8) {
        #pragma unroll
        for (int nti = 0; nti < 2; nti++) {
            int cc = (2 * wid + nti) * 8 + 2 * tq;
            bf_x[nti] = bfc[cc];
            bf_y[nti] = bfc[cc + 1];
        }
    }
    float st_s[2][2] = {{0.f,0.f},{0.f,0.f}};
    float st_q[2][2] = {{0.f,0.f},{0.f,0.f}};

    __syncthreads();

    for (int grp = 0; grp < 8; grp++) {
        int n0 = blockIdx.x * APB + grp * 4;
        if (n0 >= N) break;

        // ---- loads ----
        {
            const float* nb = nbr + (size_t)n0 * (MNBR * 64);
            for (int i = tid; i < 48 * 64; i += BD) {
                int r = i >> 6, c = i & 63;
                sNF[r * 68 + c] = tf32r(nb[i]);
            }
            for (int i = tid; i < 4 * 192; i += BD)
                sPS[i] = g_Pself[(size_t)n0 * INF_ + i];
            if (tid < 48) sJ[tid] = idx[n0 * MNBR + tid];
        }
        __syncthreads();

        // ---- edge projection MMA: warp wid -> ntiles {2wid, 2wid+1} ----
        {
            #pragma unroll
            for (int mt = 0; mt < 3; mt++) {
                int r0 = mt * 16 + qid, r1 = r0 + 8;
                float a[8][4];
                #pragma unroll
                for (int ks = 0; ks < 8; ks++) {
                    int c0 = ks * 8 + tq;
                    a[ks][0] = sNF[r0 * 68 + c0];
                    a[ks][1] = sNF[r1 * 68 + c0];
                    a[ks][2] = sNF[r0 * 68 + c0 + 4];
                    a[ks][3] = sNF[r1 * 68 + c0 + 4];
                }
                int at0 = r0 / 12, at1 = r1 / 12;
                #pragma unroll
                for (int nti = 0; nti < 2; nti++) {
                    int nt = 2 * wid + nti;
                    float d[4] = {0.f, 0.f, 0.f, 0.f};
                    const float* bw = sWE + (nt * 8 + qid) * 68;
                    #pragma unroll
                    for (int ks = 0; ks < 8; ks++)
                        mma8(d, a[ks][0], a[ks][1], a[ks][2], a[ks][3],
                             bw[ks * 8 + tq], bw[ks * 8 + tq + 4]);
                    int cc = nt * 8 + 2 * tq;
                    float2 pn0 = *(const float2*)&g_Pnbr[(size_t)sJ[r0] * INF_ + cc];
                    float2 pn1 = *(const float2*)&g_Pnbr[(size_t)sJ[r1] * INF_ + cc];
                    float2 o0, o1;
                    o0.x = d[0] + pn0.x + sPS[at0 * 192 + cc];
                    o0.y = d[1] + pn0.y + sPS[at0 * 192 + cc + 1];
                    o1.x = d[2] + pn1.x + sPS[at1 * 192 + cc];
                    o1.y = d[3] + pn1.y + sPS[at1 * 192 + cc + 1];
                    *(float2*)&sKQV[r0 * 200 + cc] = o0;
                    *(float2*)&sKQV[r1 * 200 + cc] = o1;
                }
            }
        }
        __syncthreads();

        // ---- logits[row][k] = K[row] . Q[atom,k] / 8 ----
        for (int dd = tid; dd < 576; dd += BD) {
            int row = dd / 12, k = dd - row * 12;
            int atom0 = row / 12;
            const float* Kp = sKQV + row * 200;
            const float* Qp = sKQV + (atom0 * 12 + k) * 200 + 64;
            float acc = 0.f;
            #pragma unroll 8
            for (int a = 0; a < 64; a++) acc += Kp[a] * Qp[a];
            sLG[row * 16 + k] = acc * 0.125f;
        }
        __syncthreads();

        // ---- softmax over k (48 rows) ----
        if (tid < 48) {
            float mx = -1e30f;
            #pragma unroll
            for (int k = 0; k < MNBR; k++) mx = fmaxf(mx, sLG[tid * 16 + k]);
            float s = 0.f;
            #pragma unroll
            for (int k = 0; k < MNBR; k++) {
                float e = __expf(sLG[tid * 16 + k] - mx);
                sLG[tid * 16 + k] = e;
                s += e;
            }
            float inv = 1.f / s;
            #pragma unroll
            for (int k = 0; k < MNBR; k++) sLG[tid * 16 + k] *= inv;
        }
        __syncthreads();

        // ---- attn[row][a] = sum_k w[row][k] * V[atom,k][a]  (tf32-round) ----
        #pragma unroll
        for (int s2 = 0; s2 < 8; s2++) {
            int e = tid + s2 * BD;
            int row = e >> 6, c = e & 63;
            int atom0 = row / 12;
            float acc = 0.f;
            #pragma unroll
            for (int k = 0; k < MNBR; k++)
                acc += sLG[row * 16 + k] * sKQV[(atom0 * 12 + k) * 200 + 128 + c];
            sATT[row * 68 + c] = tf32r(acc);
        }
        __syncthreads();

        // ---- gated MMA (warps 0..7): ATT[48x64] @ Wfut^T -> g_gated + stats ----
        if (wid < 8) {
            #pragma unroll
            for (int mt = 0; mt < 3; mt++) {
                int r0 = mt * 16 + qid, r1 = r0 + 8;
                float a[8][4];
                #pragma unroll
                for (int ks = 0; ks < 8; ks++) {
                    int c0 = ks * 8 + tq;
                    a[ks][0] = sATT[r0 * 68 + c0];
                    a[ks][1] = sATT[r1 * 68 + c0];
                    a[ks][2] = sATT[r0 * 68 + c0 + 4];
                    a[ks][3] = sATT[r1 * 68 + c0 + 4];
                }
                #pragma unroll
                for (int nti = 0; nti < 2; nti++) {
                    int nt = 2 * wid + nti;
                    float d[4] = {0.f, 0.f, 0.f, 0.f};
                    const float* bw = sWFU + (nt * 8 + qid) * 68;
                    #pragma unroll
                    for (int ks = 0; ks < 8; ks++)
                        mma8(d, a[ks][0], a[ks][1], a[ks][2], a[ks][3],
                             bw[ks * 8 + tq], bw[ks * 8 + tq + 4]);
                    int cc = nt * 8 + 2 * tq;
                    float v0 = d[0] + bf_x[nti];
                    float v1 = d[1] + bf_y[nti];
                    float v2 = d[2] + bf_x[nti];
                    float v3 = d[3] + bf_y[nti];
                    float* go = g_gated + ((size_t)n0 * MNBR) * 128;
                    float2 w0 = {v0, v1}, w1 = {v2, v3};
                    *(float2*)&go[r0 * 128 + cc] = w0;
                    *(float2*)&go[r1 * 128 + cc] = w1;
                    st_s[nti][0] += v0 + v2;
                    st_s[nti][1] += v1 + v3;
                    st_q[nti][0] += v0 * v0 + v2 * v2;
                    st_q[nti][1] += v1 * v1 + v3 * v3;
                }
            }
        }
        // no barrier needed here: next loads touch only sNF/sPS/sJ,
        // none of which the gated phase reads; post-load barrier covers order.
    }

    // ---- BN1 stats: reduce across the 8 lanes sharing each channel, atomicAdd ----
    if (wid < 8) {
        #pragma unroll
        for (int nti = 0; nti < 2; nti++) {
            #pragma unroll
            for (int c2 = 0; c2 < 2; c2++) {
                float s = st_s[nti][c2], q = st_q[nti][c2];
                #pragma unroll
                for (int off = 4; off < 32; off <<= 1) {
                    s += __shfl_xor_sync(0xffffffffu, s, off);
                    q += __shfl_xor_sync(0xffffffffu, q, off);
                }
                if (qid == 0) {
                    int ch = (2 * wid + nti) * 8 + 2 * tq + c2;
                    atomicAdd(&g_sum1[ch], s);
                    atomicAdd(&g_sq1[ch],  q);
                }
            }
        }
    }
}

// ---------------------------------------------------------------------------
// BN parameter kernels
// ---------------------------------------------------------------------------
__global__ void k_bn1(const float* __restrict__ g1, const float* __restrict__ b1, float invCnt) {
    int t = threadIdx.x;
    float m = g_sum1[t] * invCnt;
    float v = g_sq1[t] * invCnt - m * m;
    float sc = g1[t] * rsqrtf(v + 1e-5f);
    g_sc1[t] = sc;
    g_sh1[t] = b1[t] - m * sc;
}
__global__ void k_bn2(const float* __restrict__ g2, const float* __restrict__ b2, float invCnt) {
    int t = threadIdx.x;
    float m = g_sum2[t] * invCnt;
    float v = g_sq2[t] * invCnt - m * m;
    float sc = g2[t] * rsqrtf(v + 1e-5f);
    g_sc2[t] = sc;
    g_sh2[t] = b2[t] - m * sc;
}

// ---------------------------------------------------------------------------
// K_phase2: BN1 affine + sigmoid*softplus + sum over M; BN2 stats.
// ---------------------------------------------------------------------------
__global__ __launch_bounds__(256) void k_phase2(int N) {
    int tid = threadIdx.x;
    int sub = tid >> 6, c = tid & 63;
    float scf = g_sc1[c],      shf = g_sh1[c];
    float sch = g_sc1[c + 64], shh = g_sh1[c + 64];
    float ls = 0.f, lq = 0.f;
    int n4max = (N + 3) >> 2;
    for (int n4 = blockIdx.x; n4 < n4max; n4 += gridDim.x) {
        int n = n4 * 4 + sub;
        if (n < N) {
            const float* gp = g_gated + (size_t)n * (MNBR * 128);
            float acc = 0.f;
            #pragma unroll
            for (int m = 0; m < MNBR; m++) {
                float f = gp[m * 128 + c]      * scf + shf;
                float h = gp[m * 128 + 64 + c] * sch + shh;
                acc += sigf(f) * spf(h);
            }
            g_s[n * 64 + c] = acc;
            ls += acc;
            lq += acc * acc;
        }
    }
    atomicAdd(&g_sum2[c], ls);
    atomicAdd(&g_sq2[c],  lq);
}

// ---------------------------------------------------------------------------
// K_final: out = softplus(atom + BN2(s))
// ---------------------------------------------------------------------------
__global__ void k_final(const float* __restrict__ atom, float* __restrict__ out, int total) {
    int i = blockIdx.x * blockDim.x + threadIdx.x;
    if (i >= total) return;
    int c = i & 63;
    float v = atom[i] + g_s[i] * g_sc2[c] + g_sh2[c];
    out[i] = spf(v);
}

// ---------------------------------------------------------------------------
// kernel_launch
// ---------------------------------------------------------------------------
extern "C" void kernel_launch(void* const* d_in, const int* in_sizes, int n_in,
                              void* d_out, int out_size) {
    const float* atom = (const float*)d_in[0];
    const float* nbr  = (const float*)d_in[1];
    const int*   idx  = (const int*)  d_in[2];
    const float* WK   = (const float*)d_in[3];
    const float* WQ   = (const float*)d_in[4];
    const float* WV   = (const float*)d_in[5];
    const float* WO   = (const float*)d_in[6];
    const float* Wfc  = (const float*)d_in[7];
    const float* bfc  = (const float*)d_in[8];
    const float* bn1g = (const float*)d_in[9];
    const float* bn1b = (const float*)d_in[10];
    const float* bn2g = (const float*)d_in[11];
    const float* bn2b = (const float*)d_in[12];
    float* out = (float*)d_out;

    int N = in_sizes[0] / ATOMF;

    cudaFuncSetAttribute(k_main, cudaFuncAttributeMaxDynamicSharedMemorySize, SMEM_MAIN_BYTES);

    k_prep<<<80, 256>>>(WK, WQ, WV, Wfc, WO);
    k_proj<<<(N + 63) / 64, 384>>>(atom, WK, WQ, WV, N);
    k_main<<<(N + APB - 1) / APB, BD, SMEM_MAIN_BYTES>>>(nbr, idx, bfc, N);
    k_bn1<<<1, 128>>>(bn1g, bn1b, 1.f / (float)(N * MNBR));
    k_phase2<<<1024, 256>>>(N);
    k_bn2<<<1, 64>>>(bn2g, bn2b, 1.f / (float)N);
    k_final<<<(N * ATOMF + 255) / 256, 256>>>(atom, out, N * ATOMF);
}

// round 3
// speedup vs baseline: 1.4275x; 1.1683x over previous
#include <cuda_runtime.h>

// ---------------------------------------------------------------------------
#define NMAX   65536
#define MNBR   12
#define ATOMF  64
#define INF_   192
#define BD     384
#define APB    32      // atoms per block (8 groups of 4)

// ---------------------------------------------------------------------------
__device__ float g_Pself[NMAX * INF_];               // 48 MB
__device__ float g_Pnbr [NMAX * INF_];               // 48 MB
__device__ float g_att  [(size_t)NMAX * MNBR * 64];  // 201 MB (tf32-rounded attn)
__device__ float g_s    [NMAX * ATOMF];              // 16 MB
__device__ float g_WEt  [192 * 64];                  // edge weights, tf32
__device__ float g_Wfut [128 * 64];                  // fused W_fc@WO, tf32
__device__ float g_S    [64 * 64];                   // second moment of att
__device__ float g_svec [64];                        // sum of att
__device__ float g_sum2[64], g_sq2[64];
__device__ float g_sc1[128], g_sh1[128], g_sc2[64], g_sh2[64];

// ---------------------------------------------------------------------------
__device__ __forceinline__ void fma2(unsigned long long &d,
                                     unsigned long long a,
                                     unsigned long long b) {
    asm("fma.rn.f32x2 %0, %1, %2, %0;" : "+l"(d) : "l"(a), "l"(b));
}
__device__ __forceinline__ float2 upk(unsigned long long v) {
    float2 r;
    asm("mov.b64 {%0,%1}, %2;" : "=f"(r.x), "=f"(r.y) : "l"(v));
    return r;
}
__device__ __forceinline__ float tf32r(float x) {
    unsigned u; asm("cvt.rna.tf32.f32 %0, %1;" : "=r"(u) : "f"(x));
    return __uint_as_float(u);
}
__device__ __forceinline__ void mma8(float d[4], float a0, float a1, float a2, float a3,
                                     float b0, float b1) {
    unsigned A0 = __float_as_uint(a0), A1 = __float_as_uint(a1);
    unsigned A2 = __float_as_uint(a2), A3 = __float_as_uint(a3);
    unsigned B0 = __float_as_uint(b0), B1 = __float_as_uint(b1);
    asm volatile("mma.sync.aligned.m16n8k8.row.col.f32.tf32.tf32.f32 "
                 "{%0,%1,%2,%3}, {%4,%5,%6,%7}, {%8,%9}, {%0,%1,%2,%3};"
                 : "+f"(d[0]), "+f"(d[1]), "+f"(d[2]), "+f"(d[3])
                 : "r"(A0), "r"(A1), "r"(A2), "r"(A3), "r"(B0), "r"(B1));
}
__device__ __forceinline__ float sigf(float x) { return 1.f / (1.f + __expf(-x)); }
__device__ __forceinline__ float spf (float x) { return fmaxf(x, 0.f) + log1pf(__expf(-fabsf(x))); }

// ---------------------------------------------------------------------------
// K_prep: round WE to tf32; fuse W_fc@WO (tf32); zero accumulators.
// ---------------------------------------------------------------------------
__global__ void k_prep(const float* __restrict__ WK, const float* __restrict__ WQ,
                       const float* __restrict__ WV, const float* __restrict__ Wfc,
                       const float* __restrict__ WO) {
    int t = threadIdx.x;
    if (blockIdx.x == 0 && t < 64) {
        g_sum2[t] = 0.f; g_sq2[t] = 0.f; g_svec[t] = 0.f;
    }
    int o = blockIdx.x * 256 + t;
    if (o < 12288) {
        int j = o >> 6, f = o & 63;
        const float* W = (j < 64) ? WK : ((j < 128) ? WQ : WV);
        g_WEt[o] = tf32r(W[(j & 63) * INF_ + 128 + f]);
    } else if (o < 20480) {
        int p = o - 12288;
        int g = p >> 6, a = p & 63;
        const float* wr = Wfc + g * 256;
        float acc = 0.f;
        #pragma unroll 8
        for (int q = 0; q < 256; q++) acc += wr[q] * WO[q * 64 + a];
        g_Wfut[p] = tf32r(acc);
    } else if (o < 24576) {
        g_S[o - 20480] = 0.f;
    }
}

// ---------------------------------------------------------------------------
// K_proj: per-atom self/neighbor projections (exact f32, FFMA2).
// ---------------------------------------------------------------------------
__global__ __launch_bounds__(384) void k_proj(const float* __restrict__ atom,
                                              const float* __restrict__ WK,
                                              const float* __restrict__ WQ,
                                              const float* __restrict__ WV,
                                              int N) {
    __shared__ __align__(16) float at[16 * 68];
    int tid  = threadIdx.x;
    int half = (tid >= 192);
    int j    = half ? tid - 192 : tid;
    int proj = j >> 6, a = j & 63;
    const float* W  = (proj == 0) ? WK : ((proj == 1) ? WQ : WV);
    const float* wr = W + a * INF_ + (half ? 64 : 0);

    unsigned long long w2[32];
    #pragma unroll
    for (int f2 = 0; f2 < 32; f2++)
        w2[f2] = *(const unsigned long long*)(wr + 2 * f2);

    float* ob = half ? g_Pnbr : g_Pself;

    for (int t16 = 0; t16 < 4; t16++) {
        int n0 = (blockIdx.x * 4 + t16) * 16;
        if (n0 >= N) break;
        __syncthreads();
        for (int e = tid; e < 1024; e += 384)
            at[(e >> 6) * 68 + (e & 63)] = atom[(size_t)(n0 + (e >> 6)) * 64 + (e & 63)];
        __syncthreads();
        #pragma unroll 2
        for (int a16 = 0; a16 < 16; a16++) {
            unsigned long long acc0 = 0ull, acc1 = 0ull;
            const float* ar = at + a16 * 68;
            #pragma unroll
            for (int f2 = 0; f2 < 32; f2 += 2) {
                fma2(acc0, w2[f2],     *(const unsigned long long*)(ar + 2 * f2));
                fma2(acc1, w2[f2 + 1], *(const unsigned long long*)(ar + 2 * f2 + 2));
            }
            float2 p0 = upk(acc0), p1 = upk(acc1);
            ob[(size_t)(n0 + a16) * INF_ + j] = p0.x + p0.y + p1.x + p1.y;
        }
    }
}

// ---------------------------------------------------------------------------
// K_main: groups of 4 atoms = 48 rows.
//   phase1: NF -> smem (tf32); sKQV = Pself + Pnbr gather (f32)
//   phase2: edge MMA  (A=weights in regs, B=NF smem) accumulate into sKQV
//   phase3: logits; phase4: softmax; phase5: w@V -> sATT (tf32) + svec
//   phase6: S += ATT^T@ATT (warps 0-7) ; ATT -> global (warps 8-11)
// ---------------------------------------------------------------------------
#define O_NF   0                 // 48 x 68
#define O_KQV  3264              // 48 x 200
#define O_ATT  12864             // 48 x 68
#define O_LG   16128             // 48 x 16
#define SMEM_FLOATS 16896
#define SMEM_MAIN_BYTES (SMEM_FLOATS * 4)

__global__ __launch_bounds__(BD, 2) void k_main(const float* __restrict__ nbr,
                                                const int*   __restrict__ idx,
                                                int N) {
    extern __shared__ float sm[];
    float* sNF  = sm + O_NF;
    float* sKQV = sm + O_KQV;
    float* sATT = sm + O_ATT;
    float* sLG  = sm + O_LG;

    int tid  = threadIdx.x;
    int wid  = tid >> 5;
    int lane = tid & 31;
    int qid  = lane >> 2;
    int tq   = lane & 3;

    // edge-weight A fragments: warp wid owns channels [16*wid, 16*wid+16)
    float aw[8][4];
    {
        int ch0 = 16 * wid + qid;
        #pragma unroll
        for (int ks = 0; ks < 8; ks++) {
            int f0 = ks * 8 + tq;
            aw[ks][0] = g_WEt[ch0 * 64 + f0];
            aw[ks][1] = g_WEt[(ch0 + 8) * 64 + f0];
            aw[ks][2] = g_WEt[ch0 * 64 + f0 + 4];
            aw[ks][3] = g_WEt[(ch0 + 8) * 64 + f0 + 4];
        }
    }
    float sacc[4][4];
    #pragma unroll
    for (int i = 0; i < 4; i++)
        #pragma unroll
        for (int j = 0; j < 4; j++) sacc[i][j] = 0.f;
    float svec = 0.f;

    int hh = (tid >= 192) ? 1 : 0;
    int gch = tid - 192 * hh;     // gather channel 0..191

    for (int grp = 0; grp < 8; grp++) {
        int n0 = blockIdx.x * APB + grp * 4;
        if (n0 >= N) break;

        // ---- phase 1: NF load + KQV gather ----
        {
            const float* nb = nbr + (size_t)n0 * 768;
            #pragma unroll
            for (int s = 0; s < 8; s++) {
                int i = tid + s * 384;
                sNF[(i >> 6) * 68 + (i & 63)] = tf32r(nb[i]);
            }
            #pragma unroll 4
            for (int s = 0; s < 24; s++) {
                int e = 2 * s + hh;
                int j = idx[n0 * MNBR + e];
                sKQV[e * 200 + gch] = g_Pself[(size_t)(n0 + e / 12) * INF_ + gch]
                                    + g_Pnbr[(size_t)j * INF_ + gch];
            }
        }
        __syncthreads();

        // ---- phase 2: edge MMA ----
        {
            #pragma unroll
            for (int nt = 0; nt < 6; nt++) {
                float d[4] = {0.f, 0.f, 0.f, 0.f};
                const float* nrow = sNF + (8 * nt + qid) * 68;
                #pragma unroll
                for (int ks = 0; ks < 8; ks++) {
                    float b0 = nrow[ks * 8 + tq];
                    float b1 = nrow[ks * 8 + tq + 4];
                    mma8(d, aw[ks][0], aw[ks][1], aw[ks][2], aw[ks][3], b0, b1);
                }
                int e0  = 8 * nt + 2 * tq;
                int ch0 = 16 * wid + qid;
                sKQV[e0 * 200 + ch0]           += d[0];
                sKQV[(e0 + 1) * 200 + ch0]     += d[1];
                sKQV[e0 * 200 + ch0 + 8]       += d[2];
                sKQV[(e0 + 1) * 200 + ch0 + 8] += d[3];
            }
        }
        __syncthreads();

        // ---- phase 3: logits ----
        #pragma unroll
        for (int dd = tid; dd < 576; dd += BD) {
            int row = dd / 12, k = dd - row * 12;
            int at0 = row / 12;
            const float* Kp = sKQV + row * 200;
            const float* Qp = sKQV + (at0 * 12 + k) * 200 + 64;
            float acc = 0.f;
            #pragma unroll 8
            for (int a = 0; a < 64; a++) acc += Kp[a] * Qp[a];
            sLG[row * 16 + k] = acc * 0.125f;
        }
        __syncthreads();

        // ---- phase 4: softmax (48 rows) ----
        if (tid < 48) {
            float mx = -1e30f;
            #pragma unroll
            for (int k = 0; k < MNBR; k++) mx = fmaxf(mx, sLG[tid * 16 + k]);
            float s = 0.f;
            #pragma unroll
            for (int k = 0; k < MNBR; k++) {
                float e = __expf(sLG[tid * 16 + k] - mx);
                sLG[tid * 16 + k] = e;
                s += e;
            }
            float inv = 1.f / s;
            #pragma unroll
            for (int k = 0; k < MNBR; k++) sLG[tid * 16 + k] *= inv;
        }
        __syncthreads();

        // ---- phase 5: attn = w @ V  (tf32-round) ----
        #pragma unroll
        for (int s2 = 0; s2 < 8; s2++) {
            int e = tid + s2 * BD;
            int row = e >> 6, c = e & 63;
            int at0 = row / 12;
            float acc = 0.f;
            #pragma unroll
            for (int k = 0; k < MNBR; k++)
                acc += sLG[row * 16 + k] * sKQV[(at0 * 12 + k) * 200 + 128 + c];
            float t = tf32r(acc);
            sATT[row * 68 + c] = t;
            svec += t;
        }
        __syncthreads();

        // ---- phase 6: S-MMA (warps 0-7) + ATT global store (warps 8-11) ----
        if (wid < 8) {
            #pragma unroll
            for (int ks = 0; ks < 6; ks++) {
                int r0 = ks * 8 + tq;
                float b0 = sATT[r0 * 68 + 8 * wid + qid];
                float b1 = sATT[(r0 + 4) * 68 + 8 * wid + qid];
                #pragma unroll
                for (int mt = 0; mt < 4; mt++) {
                    float a0 = sATT[r0 * 68 + 16 * mt + qid];
                    float a1 = sATT[r0 * 68 + 16 * mt + qid + 8];
                    float a2 = sATT[(r0 + 4) * 68 + 16 * mt + qid];
                    float a3 = sATT[(r0 + 4) * 68 + 16 * mt + qid + 8];
                    mma8(sacc[mt], a0, a1, a2, a3, b0, b1);
                }
            }
        } else {
            float* go = g_att + (size_t)n0 * 768;
            #pragma unroll
            for (int i = tid - 256; i < 3072; i += 128)
                go[i] = sATT[(i >> 6) * 68 + (i & 63)];
        }
        // sATT not rewritten until phase 5 of next group (4 barriers away) — safe.
    }

    // ---- epilogue: accumulate svec + S ----
    atomicAdd(&g_svec[tid & 63], svec);
    if (wid < 8) {
        #pragma unroll
        for (int mt = 0; mt < 4; mt++) {
            int c1 = 16 * mt + qid;
            int c2 = 8 * wid + 2 * tq;
            atomicAdd(&g_S[c1 * 64 + c2],           sacc[mt][0]);
            atomicAdd(&g_S[c1 * 64 + c2 + 1],       sacc[mt][1]);
            atomicAdd(&g_S[(c1 + 8) * 64 + c2],     sacc[mt][2]);
            atomicAdd(&g_S[(c1 + 8) * 64 + c2 + 1], sacc[mt][3]);
        }
    }
}

// ---------------------------------------------------------------------------
// K_bn1: BN1 params from moment matrix. grid=128 (one block per channel g).
//   quad = w~^T S w~ ; lin = w~^T svec ; x = gated channel g
// ---------------------------------------------------------------------------
__global__ void k_bn1(const float* __restrict__ bfc, const float* __restrict__ g1,
                      const float* __restrict__ b1, float invCnt, float cnt) {
    __shared__ float sS[64 * 65];
    __shared__ float sw[64];
    __shared__ float red[4];
    int g = blockIdx.x;
    int i = threadIdx.x;           // 64
    sw[i] = g_Wfut[g * 64 + i];
    for (int l = i; l < 4096; l += 64)
        sS[(l >> 6) * 65 + (l & 63)] = g_S[l];
    __syncthreads();
    float y = 0.f;
    #pragma unroll 8
    for (int j = 0; j < 64; j++) y += sS[i * 65 + j] * sw[j];
    y *= sw[i];
    float p = sw[i] * g_svec[i];
    #pragma unroll
    for (int off = 16; off > 0; off >>= 1) {
        y += __shfl_xor_sync(0xffffffffu, y, off);
        p += __shfl_xor_sync(0xffffffffu, p, off);
    }
    if ((i & 31) == 0) { red[(i >> 5) * 2] = y; red[(i >> 5) * 2 + 1] = p; }
    __syncthreads();
    if (i == 0) {
        float quad = red[0] + red[2];
        float lin  = red[1] + red[3];
        float b    = bfc[g];
        float mean = lin * invCnt + b;
        float ex2  = (quad + 2.f * b * lin) * invCnt + b * b;
        float var  = ex2 - mean * mean;
        float sc   = g1[g] * rsqrtf(var + 1e-5f);
        g_sc1[g] = sc;
        g_sh1[g] = b1[g] - mean * sc;
    }
}

// ---------------------------------------------------------------------------
// K_gate: gated = ATT @ Wfu^T + b (tensor MMA, on-the-fly), BN1 affine,
// sigmoid*softplus, sum over M -> g_s ; accumulate BN2 stats.
// ---------------------------------------------------------------------------
#define GA_NF   0                // sA 48 x 68
#define GA_G    3264             // sG 48 x 132
#define SMEM_GATE_FLOATS 9600
#define SMEM_GATE_BYTES (SMEM_GATE_FLOATS * 4)

__global__ __launch_bounds__(BD, 2) void k_gate(const float* __restrict__ bfc, int N) {
    extern __shared__ float sm[];
    float* sA = sm + GA_NF;
    float* sG = sm + GA_G;

    int tid  = threadIdx.x;
    int wid  = tid >> 5;
    int lane = tid & 31;
    int qid  = lane >> 2;
    int tq   = lane & 3;

    // B fragments (Wfu) + bias, warps 0-7: n-tiles {2w, 2w+1}
    float bw[2][8][2];
    float bb[2][2];
    if (wid < 8) {
        #pragma unroll
        for (int nti = 0; nti < 2; nti++) {
            int nt = 2 * wid + nti;
            #pragma unroll
            for (int ks = 0; ks < 8; ks++) {
                bw[nti][ks][0] = g_Wfut[(nt * 8 + qid) * 64 + ks * 8 + tq];
                bw[nti][ks][1] = g_Wfut[(nt * 8 + qid) * 64 + ks * 8 + tq + 4];
            }
            bb[nti][0] = bfc[nt * 8 + 2 * tq];
            bb[nti][1] = bfc[nt * 8 + 2 * tq + 1];
        }
    }
    int ga = tid >> 6, gc = tid & 63;   // gate-phase coords (tid<256)
    float scf = 0.f, shf = 0.f, sch = 0.f, shh = 0.f;
    if (tid < 256) {
        scf = g_sc1[gc];      shf = g_sh1[gc];
        sch = g_sc1[gc + 64]; shh = g_sh1[gc + 64];
    }
    float ls = 0.f, lq = 0.f;

    for (int grp = 0; grp < 8; grp++) {
        int n0 = blockIdx.x * APB + grp * 4;
        if (n0 >= N) break;

        const float* ai = g_att + (size_t)n0 * 768;
        #pragma unroll
        for (int s = 0; s < 8; s++) {
            int i = tid + s * 384;
            sA[(i >> 6) * 68 + (i & 63)] = ai[i];
        }
        __syncthreads();

        if (wid < 8) {
            #pragma unroll
            for (int mt = 0; mt < 3; mt++) {
                int r0 = 16 * mt + qid;
                float a[8][4];
                #pragma unroll
                for (int ks = 0; ks < 8; ks++) {
                    int c0 = ks * 8 + tq;
                    a[ks][0] = sA[r0 * 68 + c0];
                    a[ks][1] = sA[(r0 + 8) * 68 + c0];
                    a[ks][2] = sA[r0 * 68 + c0 + 4];
                    a[ks][3] = sA[(r0 + 8) * 68 + c0 + 4];
                }
                #pragma unroll
                for (int nti = 0; nti < 2; nti++) {
                    float d[4] = {0.f, 0.f, 0.f, 0.f};
                    #pragma unroll
                    for (int ks = 0; ks < 8; ks++)
                        mma8(d, a[ks][0], a[ks][1], a[ks][2], a[ks][3],
                             bw[nti][ks][0], bw[nti][ks][1]);
                    int g0 = (2 * wid + nti) * 8 + 2 * tq;
                    sG[r0 * 132 + g0]           = d[0] + bb[nti][0];
                    sG[r0 * 132 + g0 + 1]       = d[1] + bb[nti][1];
                    sG[(r0 + 8) * 132 + g0]     = d[2] + bb[nti][0];
                    sG[(r0 + 8) * 132 + g0 + 1] = d[3] + bb[nti][1];
                }
            }
        }
        __syncthreads();

        if (tid < 256) {
            float acc = 0.f;
            #pragma unroll
            for (int m = 0; m < MNBR; m++) {
                float f = sG[(ga * 12 + m) * 132 + gc]      * scf + shf;
                float h = sG[(ga * 12 + m) * 132 + 64 + gc] * sch + shh;
                acc += sigf(f) * spf(h);
            }
            g_s[(n0 + ga) * 64 + gc] = acc;
            ls += acc;
            lq += acc * acc;
        }
        // gate reads sG finish before next load-phase barrier; safe.
    }
    if (tid < 256) {
        atomicAdd(&g_sum2[gc], ls);
        atomicAdd(&g_sq2[gc],  lq);
    }
}

// ---------------------------------------------------------------------------
__global__ void k_bn2(const float* __restrict__ g2, const float* __restrict__ b2, float invCnt) {
    int t = threadIdx.x;
    float m = g_sum2[t] * invCnt;
    float v = g_sq2[t] * invCnt - m * m;
    float sc = g2[t] * rsqrtf(v + 1e-5f);
    g_sc2[t] = sc;
    g_sh2[t] = b2[t] - m * sc;
}

__global__ void k_final(const float* __restrict__ atom, float* __restrict__ out, int total) {
    int i = blockIdx.x * blockDim.x + threadIdx.x;
    if (i >= total) return;
    int c = i & 63;
    float v = atom[i] + g_s[i] * g_sc2[c] + g_sh2[c];
    out[i] = spf(v);
}

// ---------------------------------------------------------------------------
extern "C" void kernel_launch(void* const* d_in, const int* in_sizes, int n_in,
                              void* d_out, int out_size) {
    const float* atom = (const float*)d_in[0];
    const float* nbr  = (const float*)d_in[1];
    const int*   idx  = (const int*)  d_in[2];
    const float* WK   = (const float*)d_in[3];
    const float* WQ   = (const float*)d_in[4];
    const float* WV   = (const float*)d_in[5];
    const float* WO   = (const float*)d_in[6];
    const float* Wfc  = (const float*)d_in[7];
    const float* bfc  = (const float*)d_in[8];
    const float* bn1g = (const float*)d_in[9];
    const float* bn1b = (const float*)d_in[10];
    const float* bn2g = (const float*)d_in[11];
    const float* bn2b = (const float*)d_in[12];
    float* out = (float*)d_out;

    int N = in_sizes[0] / ATOMF;
    float cnt = (float)N * MNBR;

    cudaFuncSetAttribute(k_main, cudaFuncAttributeMaxDynamicSharedMemorySize, SMEM_MAIN_BYTES);
    cudaFuncSetAttribute(k_gate, cudaFuncAttributeMaxDynamicSharedMemorySize, SMEM_GATE_BYTES);

    k_prep<<<97, 256>>>(WK, WQ, WV, Wfc, WO);
    k_proj<<<(N + 63) / 64, 384>>>(atom, WK, WQ, WV, N);
    k_main<<<(N + APB - 1) / APB, BD, SMEM_MAIN_BYTES>>>(nbr, idx, N);
    k_bn1<<<128, 64>>>(bfc, bn1g, bn1b, 1.f / cnt, cnt);
    k_gate<<<(N + APB - 1) / APB, BD, SMEM_GATE_BYTES>>>(bfc, N);
    k_bn2<<<1, 64>>>(bn2g, bn2b, 1.f / (float)N);
    k_final<<<(N * ATOMF + 255) / 256, 256>>>(atom, out, N * ATOMF);
}

// round 4
// speedup vs baseline: 1.7020x; 1.1923x over previous
#include <cuda_runtime.h>

// ---------------------------------------------------------------------------
#define NMAX   65536
#define MNBR   12
#define ATOMF  64
#define INF_   192
#define BD     384
#define APB    32      // atoms per block (8 groups of 4)

// ---------------------------------------------------------------------------
__device__ float g_Pself[NMAX * INF_];               // 48 MB
__device__ float g_Pnbr [NMAX * INF_];               // 48 MB
__device__ float g_att  [(size_t)NMAX * MNBR * 64];  // 201 MB (tf32-rounded attn)
__device__ float g_s    [NMAX * ATOMF];              // 16 MB
__device__ float g_WEt  [192 * 64];                  // edge weights, tf32
__device__ float g_Wfut [128 * 64];                  // fused W_fc@WO, tf32
__device__ float g_S    [64 * 64];                   // second moment of att
__device__ float g_svec [64];                        // sum of att
__device__ float g_sum2[64], g_sq2[64];
__device__ float g_sc1[128], g_sh1[128], g_sc2[64], g_sh2[64];

// ---------------------------------------------------------------------------
__device__ __forceinline__ void fma2(unsigned long long &d,
                                     unsigned long long a,
                                     unsigned long long b) {
    asm("fma.rn.f32x2 %0, %1, %2, %0;" : "+l"(d) : "l"(a), "l"(b));
}
__device__ __forceinline__ float2 upk(unsigned long long v) {
    float2 r;
    asm("mov.b64 {%0,%1}, %2;" : "=f"(r.x), "=f"(r.y) : "l"(v));
    return r;
}
__device__ __forceinline__ float tf32r(float x) {
    unsigned u; asm("cvt.rna.tf32.f32 %0, %1;" : "=r"(u) : "f"(x));
    return __uint_as_float(u);
}
__device__ __forceinline__ void mma8(float d[4], float a0, float a1, float a2, float a3,
                                     float b0, float b1) {
    unsigned A0 = __float_as_uint(a0), A1 = __float_as_uint(a1);
    unsigned A2 = __float_as_uint(a2), A3 = __float_as_uint(a3);
    unsigned B0 = __float_as_uint(b0), B1 = __float_as_uint(b1);
    asm volatile("mma.sync.aligned.m16n8k8.row.col.f32.tf32.tf32.f32 "
                 "{%0,%1,%2,%3}, {%4,%5,%6,%7}, {%8,%9}, {%0,%1,%2,%3};"
                 : "+f"(d[0]), "+f"(d[1]), "+f"(d[2]), "+f"(d[3])
                 : "r"(A0), "r"(A1), "r"(A2), "r"(A3), "r"(B0), "r"(B1));
}
__device__ __forceinline__ float sigf(float x) { return 1.f / (1.f + __expf(-x)); }
__device__ __forceinline__ float spf (float x) { return fmaxf(x, 0.f) + log1pf(__expf(-fabsf(x))); }

// ---------------------------------------------------------------------------
// K_prep
// ---------------------------------------------------------------------------
__global__ void k_prep(const float* __restrict__ WK, const float* __restrict__ WQ,
                       const float* __restrict__ WV, const float* __restrict__ Wfc,
                       const float* __restrict__ WO) {
    int t = threadIdx.x;
    if (blockIdx.x == 0 && t < 64) {
        g_sum2[t] = 0.f; g_sq2[t] = 0.f; g_svec[t] = 0.f;
    }
    int o = blockIdx.x * 256 + t;
    if (o < 12288) {
        int j = o >> 6, f = o & 63;
        const float* W = (j < 64) ? WK : ((j < 128) ? WQ : WV);
        g_WEt[o] = tf32r(W[(j & 63) * INF_ + 128 + f]);
    } else if (o < 20480) {
        int p = o - 12288;
        int g = p >> 6, a = p & 63;
        const float* wr = Wfc + g * 256;
        float acc = 0.f;
        #pragma unroll 8
        for (int q = 0; q < 256; q++) acc += wr[q] * WO[q * 64 + a];
        g_Wfut[p] = tf32r(acc);
    } else if (o < 24576) {
        g_S[o - 20480] = 0.f;
    }
}

// ---------------------------------------------------------------------------
// K_proj (unchanged)
// ---------------------------------------------------------------------------
__global__ __launch_bounds__(384) void k_proj(const float* __restrict__ atom,
                                              const float* __restrict__ WK,
                                              const float* __restrict__ WQ,
                                              const float* __restrict__ WV,
                                              int N) {
    __shared__ __align__(16) float at[16 * 68];
    int tid  = threadIdx.x;
    int half = (tid >= 192);
    int j    = half ? tid - 192 : tid;
    int proj = j >> 6, a = j & 63;
    const float* W  = (proj == 0) ? WK : ((proj == 1) ? WQ : WV);
    const float* wr = W + a * INF_ + (half ? 64 : 0);

    unsigned long long w2[32];
    #pragma unroll
    for (int f2 = 0; f2 < 32; f2++)
        w2[f2] = *(const unsigned long long*)(wr + 2 * f2);

    float* ob = half ? g_Pnbr : g_Pself;

    for (int t16 = 0; t16 < 4; t16++) {
        int n0 = (blockIdx.x * 4 + t16) * 16;
        if (n0 >= N) break;
        __syncthreads();
        for (int e = tid; e < 1024; e += 384)
            at[(e >> 6) * 68 + (e & 63)] = atom[(size_t)(n0 + (e >> 6)) * 64 + (e & 63)];
        __syncthreads();
        #pragma unroll 2
        for (int a16 = 0; a16 < 16; a16++) {
            unsigned long long acc0 = 0ull, acc1 = 0ull;
            const float* ar = at + a16 * 68;
            #pragma unroll
            for (int f2 = 0; f2 < 32; f2 += 2) {
                fma2(acc0, w2[f2],     *(const unsigned long long*)(ar + 2 * f2));
                fma2(acc1, w2[f2 + 1], *(const unsigned long long*)(ar + 2 * f2 + 2));
            }
            float2 p0 = upk(acc0), p1 = upk(acc1);
            ob[(size_t)(n0 + a16) * INF_ + j] = p0.x + p0.y + p1.x + p1.y;
        }
    }
}

// ---------------------------------------------------------------------------
// K_main: fully tensorized per-group pipeline.
//   P1 load/gather | P2 edge MMA | P3 logits MMA | P4 softmax+zero-pad
//   P5 w@V MMA | P6 S-MMA + att store (+svec)
// smem: sNF 48x68 | sKQV 52x200 (rows 48-51 zeroed) | sATT 48x68 | sLG 4x16x17
// ---------------------------------------------------------------------------
#define O_NF   0
#define O_KQV  3264
#define O_ATT  13664
#define O_LG   16928
#define SMEM_FLOATS 18016
#define SMEM_MAIN_BYTES (SMEM_FLOATS * 4)

__global__ __launch_bounds__(BD, 2) void k_main(const float* __restrict__ nbr,
                                                const int*   __restrict__ idx,
                                                int N) {
    extern __shared__ float sm[];
    float* sNF  = sm + O_NF;
    float* sKQV = sm + O_KQV;
    float* sATT = sm + O_ATT;
    float* sLG  = sm + O_LG;

    int tid  = threadIdx.x;
    int wid  = tid >> 5;
    int lane = tid & 31;
    int qid  = lane >> 2;
    int tq   = lane & 3;

    // edge-weight A fragments: warp wid owns channels [16*wid, 16*wid+16)
    float aw[8][4];
    {
        int ch0 = 16 * wid + qid;
        #pragma unroll
        for (int ks = 0; ks < 8; ks++) {
            int f0 = ks * 8 + tq;
            aw[ks][0] = g_WEt[ch0 * 64 + f0];
            aw[ks][1] = g_WEt[(ch0 + 8) * 64 + f0];
            aw[ks][2] = g_WEt[ch0 * 64 + f0 + 4];
            aw[ks][3] = g_WEt[(ch0 + 8) * 64 + f0 + 4];
        }
    }
    float sacc[4][4];
    #pragma unroll
    for (int i = 0; i < 4; i++)
        #pragma unroll
        for (int j = 0; j < 4; j++) sacc[i][j] = 0.f;
    float svec = 0.f;

    int hh = (tid >= 192) ? 1 : 0;
    int gch = tid - 192 * hh;

    // zero pad rows 48-51 of sKQV (read by P3/P5 fragments for atom 3)
    for (int i = tid; i < 4 * 200; i += BD) sKQV[48 * 200 + i] = 0.f;

    for (int grp = 0; grp < 8; grp++) {
        int n0 = blockIdx.x * APB + grp * 4;
        if (n0 >= N) break;

        // ---- P1: NF load + KQV gather ----
        {
            const float* nb = nbr + (size_t)n0 * 768;
            #pragma unroll
            for (int s = 0; s < 8; s++) {
                int i = tid + s * 384;
                sNF[(i >> 6) * 68 + (i & 63)] = tf32r(nb[i]);
            }
            #pragma unroll 4
            for (int s = 0; s < 24; s++) {
                int e = 2 * s + hh;
                int j = idx[n0 * MNBR + e];
                sKQV[e * 200 + gch] = g_Pself[(size_t)(n0 + e / 12) * INF_ + gch]
                                    + g_Pnbr[(size_t)j * INF_ + gch];
            }
        }
        __syncthreads();

        // ---- P2: edge MMA (A=weights in regs, B=NF) ----
        {
            #pragma unroll
            for (int nt = 0; nt < 6; nt++) {
                float d[4] = {0.f, 0.f, 0.f, 0.f};
                const float* nrow = sNF + (8 * nt + qid) * 68;
                #pragma unroll
                for (int ks = 0; ks < 8; ks++) {
                    float b0 = nrow[ks * 8 + tq];
                    float b1 = nrow[ks * 8 + tq + 4];
                    mma8(d, aw[ks][0], aw[ks][1], aw[ks][2], aw[ks][3], b0, b1);
                }
                int e0  = 8 * nt + 2 * tq;
                int ch0 = 16 * wid + qid;
                sKQV[e0 * 200 + ch0]           += d[0];
                sKQV[(e0 + 1) * 200 + ch0]     += d[1];
                sKQV[e0 * 200 + ch0 + 8]       += d[2];
                sKQV[(e0 + 1) * 200 + ch0 + 8] += d[3];
            }
        }
        __syncthreads();

        // ---- P3: logits MMA (per-atom 16x16, k=64) : warps 0-7 ----
        if (wid < 8) {
            int a  = wid >> 1;
            int nt = wid & 1;
            int r0 = 12 * a;
            float d[4] = {0.f, 0.f, 0.f, 0.f};
            #pragma unroll
            for (int s = 0; s < 8; s++) {
                int f = 8 * s + tq;
                float a0 = tf32r(sKQV[(r0 + qid) * 200 + f]);
                float a1 = tf32r(sKQV[(r0 + qid + 8) * 200 + f]);
                float a2 = tf32r(sKQV[(r0 + qid) * 200 + f + 4]);
                float a3 = tf32r(sKQV[(r0 + qid + 8) * 200 + f + 4]);
                float b0 = tf32r(sKQV[(r0 + 8 * nt + qid) * 200 + 64 + f]);
                float b1 = tf32r(sKQV[(r0 + 8 * nt + qid) * 200 + 64 + f + 4]);
                mma8(d, a0, a1, a2, a3, b0, b1);
            }
            float* lg = sLG + a * 272;
            int c = 8 * nt + 2 * tq;
            lg[qid * 17 + c]           = d[0] * 0.125f;
            lg[qid * 17 + c + 1]       = d[1] * 0.125f;
            lg[(qid + 8) * 17 + c]     = d[2] * 0.125f;
            lg[(qid + 8) * 17 + c + 1] = d[3] * 0.125f;
        }
        __syncthreads();

        // ---- P4: softmax rows + zero padding (64 threads) ----
        if (tid < 64) {
            int a = tid >> 4, r = tid & 15;
            float* lg = sLG + a * 272 + r * 17;
            if (r < 12) {
                float l[12];
                float mx = -1e30f;
                #pragma unroll
                for (int k = 0; k < 12; k++) { l[k] = lg[k]; mx = fmaxf(mx, l[k]); }
                float s = 0.f;
                #pragma unroll
                for (int k = 0; k < 12; k++) { l[k] = __expf(l[k] - mx); s += l[k]; }
                float inv = 1.f / s;
                #pragma unroll
                for (int k = 0; k < 12; k++) lg[k] = tf32r(l[k] * inv);
                lg[12] = 0.f; lg[13] = 0.f; lg[14] = 0.f; lg[15] = 0.f;
            } else {
                #pragma unroll
                for (int k = 0; k < 16; k++) lg[k] = 0.f;
            }
        }
        __syncthreads();

        // ---- P5: attn = W @ V MMA (per-atom m16 n64 k16) : warps 0-7 ----
        if (wid < 8) {
            int a = wid >> 1;
            int ntb = (wid & 1) * 4;
            const float* lg = sLG + a * 272;
            float af[2][4];
            #pragma unroll
            for (int s = 0; s < 2; s++) {
                int k = 8 * s + tq;
                af[s][0] = lg[qid * 17 + k];
                af[s][1] = lg[(qid + 8) * 17 + k];
                af[s][2] = lg[qid * 17 + k + 4];
                af[s][3] = lg[(qid + 8) * 17 + k + 4];
            }
            #pragma unroll
            for (int j = 0; j < 4; j++) {
                int nt = ntb + j;
                float d[4] = {0.f, 0.f, 0.f, 0.f};
                #pragma unroll
                for (int s = 0; s < 2; s++) {
                    int kr = 12 * a + 8 * s + tq;
                    float b0 = tf32r(sKQV[kr * 200 + 128 + 8 * nt + qid]);
                    float b1 = tf32r(sKQV[(kr + 4) * 200 + 128 + 8 * nt + qid]);
                    mma8(d, af[s][0], af[s][1], af[s][2], af[s][3], b0, b1);
                }
                int col = 8 * nt + 2 * tq;
                int row = 12 * a + qid;
                sATT[row * 68 + col]     = tf32r(d[0]);
                sATT[row * 68 + col + 1] = tf32r(d[1]);
                if (qid < 4) {
                    sATT[(row + 8) * 68 + col]     = tf32r(d[2]);
                    sATT[(row + 8) * 68 + col + 1] = tf32r(d[3]);
                }
            }
        }
        __syncthreads();

        // ---- P6: S-MMA (warps 0-7) + att store & svec (warps 8-11) ----
        if (wid < 8) {
            int mt  = wid >> 1;
            int ntb = (wid & 1) * 4;
            #pragma unroll
            for (int ks = 0; ks < 6; ks++) {
                int kr = 8 * ks + tq;
                float a0 = sATT[kr * 68 + 16 * mt + qid];
                float a1 = sATT[kr * 68 + 16 * mt + qid + 8];
                float a2 = sATT[(kr + 4) * 68 + 16 * mt + qid];
                float a3 = sATT[(kr + 4) * 68 + 16 * mt + qid + 8];
                #pragma unroll
                for (int j = 0; j < 4; j++) {
                    int nt = ntb + j;
                    float b0 = sATT[kr * 68 + 8 * nt + qid];
                    float b1 = sATT[(kr + 4) * 68 + 8 * nt + qid];
                    mma8(sacc[j], a0, a1, a2, a3, b0, b1);
                }
            }
        } else {
            float* go = g_att + (size_t)n0 * 768;
            #pragma unroll
            for (int i = tid - 256; i < 3072; i += 128) {
                float v = sATT[(i >> 6) * 68 + (i & 63)];
                go[i] = v;
                svec += v;
            }
        }
    }

    // ---- epilogue ----
    if (wid >= 8) atomicAdd(&g_svec[tid & 63], svec);
    if (wid < 8) {
        int mt  = wid >> 1;
        int ntb = (wid & 1) * 4;
        #pragma unroll
        for (int j = 0; j < 4; j++) {
            int c1 = 16 * mt + qid;
            int c2 = 8 * (ntb + j) + 2 * tq;
            atomicAdd(&g_S[c1 * 64 + c2],           sacc[j][0]);
            atomicAdd(&g_S[c1 * 64 + c2 + 1],       sacc[j][1]);
            atomicAdd(&g_S[(c1 + 8) * 64 + c2],     sacc[j][2]);
            atomicAdd(&g_S[(c1 + 8) * 64 + c2 + 1], sacc[j][3]);
        }
    }
}

// ---------------------------------------------------------------------------
// K_bn1 (moment trick, unchanged)
// ---------------------------------------------------------------------------
__global__ void k_bn1(const float* __restrict__ bfc, const float* __restrict__ g1,
                      const float* __restrict__ b1, float invCnt, float cnt) {
    __shared__ float sS[64 * 65];
    __shared__ float sw[64];
    __shared__ float red[4];
    int g = blockIdx.x;
    int i = threadIdx.x;
    sw[i] = g_Wfut[g * 64 + i];
    for (int l = i; l < 4096; l += 64)
        sS[(l >> 6) * 65 + (l & 63)] = g_S[l];
    __syncthreads();
    float y = 0.f;
    #pragma unroll 8
    for (int j = 0; j < 64; j++) y += sS[i * 65 + j] * sw[j];
    y *= sw[i];
    float p = sw[i] * g_svec[i];
    #pragma unroll
    for (int off = 16; off > 0; off >>= 1) {
        y += __shfl_xor_sync(0xffffffffu, y, off);
        p += __shfl_xor_sync(0xffffffffu, p, off);
    }
    if ((i & 31) == 0) { red[(i >> 5) * 2] = y; red[(i >> 5) * 2 + 1] = p; }
    __syncthreads();
    if (i == 0) {
        float quad = red[0] + red[2];
        float lin  = red[1] + red[3];
        float b    = bfc[g];
        float mean = lin * invCnt + b;
        float ex2  = (quad + 2.f * b * lin) * invCnt + b * b;
        float var  = ex2 - mean * mean;
        float sc   = g1[g] * rsqrtf(var + 1e-5f);
        g_sc1[g] = sc;
        g_sh1[g] = b1[g] - mean * sc;
    }
}

// ---------------------------------------------------------------------------
// K_gate (unchanged from round 3)
// ---------------------------------------------------------------------------
#define GA_NF   0
#define GA_G    3264
#define SMEM_GATE_FLOATS 9600
#define SMEM_GATE_BYTES (SMEM_GATE_FLOATS * 4)

__global__ __launch_bounds__(BD, 2) void k_gate(const float* __restrict__ bfc, int N) {
    extern __shared__ float sm[];
    float* sA = sm + GA_NF;
    float* sG = sm + GA_G;

    int tid  = threadIdx.x;
    int wid  = tid >> 5;
    int lane = tid & 31;
    int qid  = lane >> 2;
    int tq   = lane & 3;

    float bw[2][8][2];
    float bb[2][2];
    if (wid < 8) {
        #pragma unroll
        for (int nti = 0; nti < 2; nti++) {
            int nt = 2 * wid + nti;
            #pragma unroll
            for (int ks = 0; ks < 8; ks++) {
                bw[nti][ks][0] = g_Wfut[(nt * 8 + qid) * 64 + ks * 8 + tq];
                bw[nti][ks][1] = g_Wfut[(nt * 8 + qid) * 64 + ks * 8 + tq + 4];
            }
            bb[nti][0] = bfc[nt * 8 + 2 * tq];
            bb[nti][1] = bfc[nt * 8 + 2 * tq + 1];
        }
    }
    int ga = tid >> 6, gc = tid & 63;
    float scf = 0.f, shf = 0.f, sch = 0.f, shh = 0.f;
    if (tid < 256) {
        scf = g_sc1[gc];      shf = g_sh1[gc];
        sch = g_sc1[gc + 64]; shh = g_sh1[gc + 64];
    }
    float ls = 0.f, lq = 0.f;

    for (int grp = 0; grp < 8; grp++) {
        int n0 = blockIdx.x * APB + grp * 4;
        if (n0 >= N) break;

        const float* ai = g_att + (size_t)n0 * 768;
        #pragma unroll
        for (int s = 0; s < 8; s++) {
            int i = tid + s * 384;
            sA[(i >> 6) * 68 + (i & 63)] = ai[i];
        }
        __syncthreads();

        if (wid < 8) {
            #pragma unroll
            for (int mt = 0; mt < 3; mt++) {
                int r0 = 16 * mt + qid;
                float a[8][4];
                #pragma unroll
                for (int ks = 0; ks < 8; ks++) {
                    int c0 = ks * 8 + tq;
                    a[ks][0] = sA[r0 * 68 + c0];
                    a[ks][1] = sA[(r0 + 8) * 68 + c0];
                    a[ks][2] = sA[r0 * 68 + c0 + 4];
                    a[ks][3] = sA[(r0 + 8) * 68 + c0 + 4];
                }
                #pragma unroll
                for (int nti = 0; nti < 2; nti++) {
                    float d[4] = {0.f, 0.f, 0.f, 0.f};
                    #pragma unroll
                    for (int ks = 0; ks < 8; ks++)
                        mma8(d, a[ks][0], a[ks][1], a[ks][2], a[ks][3],
                             bw[nti][ks][0], bw[nti][ks][1]);
                    int g0 = (2 * wid + nti) * 8 + 2 * tq;
                    sG[r0 * 132 + g0]           = d[0] + bb[nti][0];
                    sG[r0 * 132 + g0 + 1]       = d[1] + bb[nti][1];
                    sG[(r0 + 8) * 132 + g0]     = d[2] + bb[nti][0];
                    sG[(r0 + 8) * 132 + g0 + 1] = d[3] + bb[nti][1];
                }
            }
        }
        __syncthreads();

        if (tid < 256) {
            float acc = 0.f;
            #pragma unroll
            for (int m = 0; m < MNBR; m++) {
                float f = sG[(ga * 12 + m) * 132 + gc]      * scf + shf;
                float h = sG[(ga * 12 + m) * 132 + 64 + gc] * sch + shh;
                acc += sigf(f) * spf(h);
            }
            g_s[(n0 + ga) * 64 + gc] = acc;
            ls += acc;
            lq += acc * acc;
        }
    }
    if (tid < 256) {
        atomicAdd(&g_sum2[gc], ls);
        atomicAdd(&g_sq2[gc],  lq);
    }
}

// ---------------------------------------------------------------------------
__global__ void k_bn2(const float* __restrict__ g2, const float* __restrict__ b2, float invCnt) {
    int t = threadIdx.x;
    float m = g_sum2[t] * invCnt;
    float v = g_sq2[t] * invCnt - m * m;
    float sc = g2[t] * rsqrtf(v + 1e-5f);
    g_sc2[t] = sc;
    g_sh2[t] = b2[t] - m * sc;
}

__global__ void k_final(const float* __restrict__ atom, float* __restrict__ out, int total) {
    int i = blockIdx.x * blockDim.x + threadIdx.x;
    if (i >= total) return;
    int c = i & 63;
    float v = atom[i] + g_s[i] * g_sc2[c] + g_sh2[c];
    out[i] = spf(v);
}

// ---------------------------------------------------------------------------
extern "C" void kernel_launch(void* const* d_in, const int* in_sizes, int n_in,
                              void* d_out, int out_size) {
    const float* atom = (const float*)d_in[0];
    const float* nbr  = (const float*)d_in[1];
    const int*   idx  = (const int*)  d_in[2];
    const float* WK   = (const float*)d_in[3];
    const float* WQ   = (const float*)d_in[4];
    const float* WV   = (const float*)d_in[5];
    const float* WO   = (const float*)d_in[6];
    const float* Wfc  = (const float*)d_in[7];
    const float* bfc  = (const float*)d_in[8];
    const float* bn1g = (const float*)d_in[9];
    const float* bn1b = (const float*)d_in[10];
    const float* bn2g = (const float*)d_in[11];
    const float* bn2b = (const float*)d_in[12];
    float* out = (float*)d_out;

    int N = in_sizes[0] / ATOMF;
    float cnt = (float)N * MNBR;

    cudaFuncSetAttribute(k_main, cudaFuncAttributeMaxDynamicSharedMemorySize, SMEM_MAIN_BYTES);
    cudaFuncSetAttribute(k_gate, cudaFuncAttributeMaxDynamicSharedMemorySize, SMEM_GATE_BYTES);

    k_prep<<<97, 256>>>(WK, WQ, WV, Wfc, WO);
    k_proj<<<(N + 63) / 64, 384>>>(atom, WK, WQ, WV, N);
    k_main<<<(N + APB - 1) / APB, BD, SMEM_MAIN_BYTES>>>(nbr, idx, N);
    k_bn1<<<128, 64>>>(bfc, bn1g, bn1b, 1.f / cnt, cnt);
    k_gate<<<(N + APB - 1) / APB, BD, SMEM_GATE_BYTES>>>(bfc, N);
    k_bn2<<<1, 64>>>(bn2g, bn2b, 1.f / (float)N);
    k_final<<<(N * ATOMF + 255) / 256, 256>>>(atom, out, N * ATOMF);
}

// round 5
// speedup vs baseline: 2.0654x; 1.2135x over previous
#include <cuda_runtime.h>

// ---------------------------------------------------------------------------
#define NMAX   65536
#define MNBR   12
#define ATOMF  64
#define INF_   192
#define BD     384
#define GBD    256
#define APB    32      // atoms per block (8 groups of 4)

// ---------------------------------------------------------------------------
__device__ float g_Pself[NMAX * INF_];               // 48 MB
__device__ float g_Pnbr [NMAX * INF_];               // 48 MB
__device__ float g_att  [(size_t)NMAX * MNBR * 64];  // 201 MB
__device__ float g_s    [NMAX * ATOMF];              // 16 MB
__device__ float g_WEt  [192 * 64];                  // edge weights, tf32
__device__ float g_Wall [384 * 64];                  // [self|nbr] proj weights, tf32
__device__ float g_Wfut [128 * 64];                  // fused W_fc@WO, tf32
__device__ float g_S    [64 * 64];
__device__ float g_svec [64];
__device__ float g_sum2[64], g_sq2[64];
__device__ float g_sc1[128], g_sh1[128], g_sc2[64], g_sh2[64];

// ---------------------------------------------------------------------------
__device__ __forceinline__ float tf32r(float x) {
    unsigned u; asm("cvt.rna.tf32.f32 %0, %1;" : "=r"(u) : "f"(x));
    return __uint_as_float(u);
}
__device__ __forceinline__ void mma8(float d[4], float a0, float a1, float a2, float a3,
                                     float b0, float b1) {
    unsigned A0 = __float_as_uint(a0), A1 = __float_as_uint(a1);
    unsigned A2 = __float_as_uint(a2), A3 = __float_as_uint(a3);
    unsigned B0 = __float_as_uint(b0), B1 = __float_as_uint(b1);
    asm volatile("mma.sync.aligned.m16n8k8.row.col.f32.tf32.tf32.f32 "
                 "{%0,%1,%2,%3}, {%4,%5,%6,%7}, {%8,%9}, {%0,%1,%2,%3};"
                 : "+f"(d[0]), "+f"(d[1]), "+f"(d[2]), "+f"(d[3])
                 : "r"(A0), "r"(A1), "r"(A2), "r"(A3), "r"(B0), "r"(B1));
}
__device__ __forceinline__ float sigf(float x) { return 1.f / (1.f + __expf(-x)); }
__device__ __forceinline__ float spf2(float x) {
    return fmaxf(x, 0.f) + __logf(1.f + __expf(-fabsf(x)));
}

// ---------------------------------------------------------------------------
// K_prep: tf32-round WEt, Wall (self|nbr proj weights); fuse W_fc@WO; zero stats.
// grid 192 x 256.
// ---------------------------------------------------------------------------
__global__ void k_prep(const float* __restrict__ WK, const float* __restrict__ WQ,
                       const float* __restrict__ WV, const float* __restrict__ Wfc,
                       const float* __restrict__ WO) {
    int t = threadIdx.x;
    if (blockIdx.x == 0 && t < 64) {
        g_sum2[t] = 0.f; g_sq2[t] = 0.f; g_svec[t] = 0.f;
    }
    int o = blockIdx.x * 256 + t;
    if (o < 12288) {
        int j = o >> 6, f = o & 63;
        const float* W = (j < 64) ? WK : ((j < 128) ? WQ : WV);
        g_WEt[o] = tf32r(W[(j & 63) * INF_ + 128 + f]);
    } else if (o < 36864) {
        int p = o - 12288;
        int j = p >> 6, f = p & 63;
        int half = (j >= 192);
        int jj = half ? j - 192 : j;
        const float* W = (jj < 64) ? WK : ((jj < 128) ? WQ : WV);
        g_Wall[p] = tf32r(W[(jj & 63) * INF_ + (half ? 64 : 0) + f]);
    } else if (o < 45056) {
        int p = o - 36864;
        int g = p >> 6, a = p & 63;
        const float* wr = Wfc + g * 256;
        float acc = 0.f;
        #pragma unroll 8
        for (int q = 0; q < 256; q++) acc += wr[q] * WO[q * 64 + a];
        g_Wfut[p] = tf32r(acc);
    } else if (o < 49152) {
        g_S[o - 45056] = 0.f;
    }
}

// ---------------------------------------------------------------------------
// K_projT: tensor-core per-atom projections. Block = 48 atoms, 12 warps x 16 ch,
// two halves (self-cols then nbr-cols), weights reloaded per half from g_Wall.
// ---------------------------------------------------------------------------
__global__ __launch_bounds__(384, 2) void k_projT(const float* __restrict__ atom, int N) {
    __shared__ float sAT[48 * 68];
    int tid = threadIdx.x, wid = tid >> 5, lane = tid & 31;
    int qid = lane >> 2, tq = lane & 3;
    int n0 = blockIdx.x * 48;

    #pragma unroll
    for (int s = 0; s < 8; s++) {
        int i = tid + s * 384;
        int r = i >> 6, c = i & 63;
        int n = n0 + r;
        float v = (n < N) ? atom[(size_t)n * 64 + c] : 0.f;
        sAT[r * 68 + c] = tf32r(v);
    }
    __syncthreads();

    #pragma unroll
    for (int half = 0; half < 2; half++) {
        const float* Wsrc = g_Wall + (half * 192 + wid * 16) * 64;
        float aw[8][4];
        #pragma unroll
        for (int ks = 0; ks < 8; ks++) {
            int f0 = ks * 8 + tq;
            aw[ks][0] = Wsrc[qid * 64 + f0];
            aw[ks][1] = Wsrc[(qid + 8) * 64 + f0];
            aw[ks][2] = Wsrc[qid * 64 + f0 + 4];
            aw[ks][3] = Wsrc[(qid + 8) * 64 + f0 + 4];
        }
        float* ob = half ? g_Pnbr : g_Pself;
        #pragma unroll
        for (int nt = 0; nt < 6; nt++) {
            float d[4] = {0.f, 0.f, 0.f, 0.f};
            const float* ar = sAT + (8 * nt + qid) * 68;
            #pragma unroll
            for (int ks = 0; ks < 8; ks++)
                mma8(d, aw[ks][0], aw[ks][1], aw[ks][2], aw[ks][3],
                     ar[ks * 8 + tq], ar[ks * 8 + tq + 4]);
            int r0  = 8 * nt + 2 * tq;
            int ch0 = wid * 16 + qid;
            if (n0 + r0 < N) {
                ob[(size_t)(n0 + r0) * INF_ + ch0]     = d[0];
                ob[(size_t)(n0 + r0) * INF_ + ch0 + 8] = d[2];
            }
            if (n0 + r0 + 1 < N) {
                ob[(size_t)(n0 + r0 + 1) * INF_ + ch0]     = d[1];
                ob[(size_t)(n0 + r0 + 1) * INF_ + ch0 + 8] = d[3];
            }
        }
    }
}

// ---------------------------------------------------------------------------
// K_main: tensorized pipeline; K/Q/V pre-rounded in P2 epilogue.
// ---------------------------------------------------------------------------
#define O_NF   0
#define O_KQV  3264
#define O_ATT  13664
#define O_LG   16928
#define SMEM_FLOATS 18016
#define SMEM_MAIN_BYTES (SMEM_FLOATS * 4)

__global__ __launch_bounds__(BD, 2) void k_main(const float* __restrict__ nbr,
                                                const int*   __restrict__ idx,
                                                int N) {
    extern __shared__ float sm[];
    float* sNF  = sm + O_NF;
    float* sKQV = sm + O_KQV;
    float* sATT = sm + O_ATT;
    float* sLG  = sm + O_LG;

    int tid  = threadIdx.x;
    int wid  = tid >> 5;
    int lane = tid & 31;
    int qid  = lane >> 2;
    int tq   = lane & 3;

    float aw[8][4];
    {
        int ch0 = 16 * wid + qid;
        #pragma unroll
        for (int ks = 0; ks < 8; ks++) {
            int f0 = ks * 8 + tq;
            aw[ks][0] = g_WEt[ch0 * 64 + f0];
            aw[ks][1] = g_WEt[(ch0 + 8) * 64 + f0];
            aw[ks][2] = g_WEt[ch0 * 64 + f0 + 4];
            aw[ks][3] = g_WEt[(ch0 + 8) * 64 + f0 + 4];
        }
    }
    float sacc[4][4];
    #pragma unroll
    for (int i = 0; i < 4; i++)
        #pragma unroll
        for (int j = 0; j < 4; j++) sacc[i][j] = 0.f;
    float svec = 0.f;

    int hh = (tid >= 192) ? 1 : 0;
    int gch = tid - 192 * hh;

    for (int i = tid; i < 4 * 200; i += BD) sKQV[48 * 200 + i] = 0.f;

    for (int grp = 0; grp < 8; grp++) {
        int n0 = blockIdx.x * APB + grp * 4;
        if (n0 >= N) break;

        // ---- P1: NF load + KQV gather (Pself staged in regs) ----
        {
            const float* nb = nbr + (size_t)n0 * 768;
            #pragma unroll
            for (int s = 0; s < 8; s++) {
                int i = tid + s * 384;
                sNF[(i >> 6) * 68 + (i & 63)] = tf32r(nb[i]);
            }
            float ps0 = g_Pself[(size_t)n0 * INF_ + gch];
            float ps1 = g_Pself[(size_t)(n0 + 1) * INF_ + gch];
            float ps2 = g_Pself[(size_t)(n0 + 2) * INF_ + gch];
            float ps3 = g_Pself[(size_t)(n0 + 3) * INF_ + gch];
            #pragma unroll
            for (int s = 0; s < 24; s++) {
                int e = 2 * s + hh;
                int j = idx[n0 * MNBR + e];
                float ps = (s < 6) ? ps0 : ((s < 12) ? ps1 : ((s < 18) ? ps2 : ps3));
                sKQV[e * 200 + gch] = ps + g_Pnbr[(size_t)j * INF_ + gch];
            }
        }
        __syncthreads();

        // ---- P2: edge MMA; epilogue rounds K/Q/V to tf32 ----
        {
            #pragma unroll
            for (int nt = 0; nt < 6; nt++) {
                float d[4] = {0.f, 0.f, 0.f, 0.f};
                const float* nrow = sNF + (8 * nt + qid) * 68;
                #pragma unroll
                for (int ks = 0; ks < 8; ks++) {
                    float b0 = nrow[ks * 8 + tq];
                    float b1 = nrow[ks * 8 + tq + 4];
                    mma8(d, aw[ks][0], aw[ks][1], aw[ks][2], aw[ks][3], b0, b1);
                }
                int e0  = 8 * nt + 2 * tq;
                int ch0 = 16 * wid + qid;
                sKQV[e0 * 200 + ch0]           = tf32r(sKQV[e0 * 200 + ch0] + d[0]);
                sKQV[(e0 + 1) * 200 + ch0]     = tf32r(sKQV[(e0 + 1) * 200 + ch0] + d[1]);
                sKQV[e0 * 200 + ch0 + 8]       = tf32r(sKQV[e0 * 200 + ch0 + 8] + d[2]);
                sKQV[(e0 + 1) * 200 + ch0 + 8] = tf32r(sKQV[(e0 + 1) * 200 + ch0 + 8] + d[3]);
            }
        }
        __syncthreads();

        // ---- P3: logits MMA (per-atom 16x16, k=64) : warps 0-7 ----
        if (wid < 8) {
            int a  = wid >> 1;
            int nt = wid & 1;
            int r0 = 12 * a;
            float d[4] = {0.f, 0.f, 0.f, 0.f};
            #pragma unroll
            for (int s = 0; s < 8; s++) {
                int f = 8 * s + tq;
                float a0 = sKQV[(r0 + qid) * 200 + f];
                float a1 = sKQV[(r0 + qid + 8) * 200 + f];
                float a2 = sKQV[(r0 + qid) * 200 + f + 4];
                float a3 = sKQV[(r0 + qid + 8) * 200 + f + 4];
                float b0 = sKQV[(r0 + 8 * nt + qid) * 200 + 64 + f];
                float b1 = sKQV[(r0 + 8 * nt + qid) * 200 + 64 + f + 4];
                mma8(d, a0, a1, a2, a3, b0, b1);
            }
            float* lg = sLG + a * 272;
            int c = 8 * nt + 2 * tq;
            lg[qid * 17 + c]           = d[0] * 0.125f;
            lg[qid * 17 + c + 1]       = d[1] * 0.125f;
            lg[(qid + 8) * 17 + c]     = d[2] * 0.125f;
            lg[(qid + 8) * 17 + c + 1] = d[3] * 0.125f;
        }
        __syncthreads();

        // ---- P4: softmax + zero padding ----
        if (tid < 64) {
            int a = tid >> 4, r = tid & 15;
            float* lg = sLG + a * 272 + r * 17;
            if (r < 12) {
                float l[12];
                float mx = -1e30f;
                #pragma unroll
                for (int k = 0; k < 12; k++) { l[k] = lg[k]; mx = fmaxf(mx, l[k]); }
                float s = 0.f;
                #pragma unroll
                for (int k = 0; k < 12; k++) { l[k] = __expf(l[k] - mx); s += l[k]; }
                float inv = 1.f / s;
                #pragma unroll
                for (int k = 0; k < 12; k++) lg[k] = tf32r(l[k] * inv);
                lg[12] = 0.f; lg[13] = 0.f; lg[14] = 0.f; lg[15] = 0.f;
            } else {
                #pragma unroll
                for (int k = 0; k < 16; k++) lg[k] = 0.f;
            }
        }
        __syncthreads();

        // ---- P5: attn = W @ V MMA : warps 0-7 ----
        if (wid < 8) {
            int a = wid >> 1;
            int ntb = (wid & 1) * 4;
            const float* lg = sLG + a * 272;
            float af[2][4];
            #pragma unroll
            for (int s = 0; s < 2; s++) {
                int k = 8 * s + tq;
                af[s][0] = lg[qid * 17 + k];
                af[s][1] = lg[(qid + 8) * 17 + k];
                af[s][2] = lg[qid * 17 + k + 4];
                af[s][3] = lg[(qid + 8) * 17 + k + 4];
            }
            #pragma unroll
            for (int j = 0; j < 4; j++) {
                int nt = ntb + j;
                float d[4] = {0.f, 0.f, 0.f, 0.f};
                #pragma unroll
                for (int s = 0; s < 2; s++) {
                    int kr = 12 * a + 8 * s + tq;
                    float b0 = sKQV[kr * 200 + 128 + 8 * nt + qid];
                    float b1 = sKQV[(kr + 4) * 200 + 128 + 8 * nt + qid];
                    mma8(d, af[s][0], af[s][1], af[s][2], af[s][3], b0, b1);
                }
                int col = 8 * nt + 2 * tq;
                int row = 12 * a + qid;
                sATT[row * 68 + col]     = tf32r(d[0]);
                sATT[row * 68 + col + 1] = tf32r(d[1]);
                if (qid < 4) {
                    sATT[(row + 8) * 68 + col]     = tf32r(d[2]);
                    sATT[(row + 8) * 68 + col + 1] = tf32r(d[3]);
                }
            }
        }
        __syncthreads();

        // ---- P6: S-MMA (warps 0-7) + att store & svec (warps 8-11) ----
        if (wid < 8) {
            int mt  = wid >> 1;
            int ntb = (wid & 1) * 4;
            #pragma unroll
            for (int ks = 0; ks < 6; ks++) {
                int kr = 8 * ks + tq;
                float a0 = sATT[kr * 68 + 16 * mt + qid];
                float a1 = sATT[kr * 68 + 16 * mt + qid + 8];
                float a2 = sATT[(kr + 4) * 68 + 16 * mt + qid];
                float a3 = sATT[(kr + 4) * 68 + 16 * mt + qid + 8];
                #pragma unroll
                for (int j = 0; j < 4; j++) {
                    int nt = ntb + j;
                    float b0 = sATT[kr * 68 + 8 * nt + qid];
                    float b1 = sATT[(kr + 4) * 68 + 8 * nt + qid];
                    mma8(sacc[j], a0, a1, a2, a3, b0, b1);
                }
            }
        } else {
            float* go = g_att + (size_t)n0 * 768;
            #pragma unroll
            for (int i = tid - 256; i < 3072; i += 128) {
                float v = sATT[(i >> 6) * 68 + (i & 63)];
                go[i] = v;
                svec += v;
            }
        }
    }

    // ---- epilogue ----
    if (wid >= 8) atomicAdd(&g_svec[tid & 63], svec);
    if (wid < 8) {
        int mt  = wid >> 1;
        int ntb = (wid & 1) * 4;
        #pragma unroll
        for (int j = 0; j < 4; j++) {
            int c1 = 16 * mt + qid;
            int c2 = 8 * (ntb + j) + 2 * tq;
            atomicAdd(&g_S[c1 * 64 + c2],           sacc[j][0]);
            atomicAdd(&g_S[c1 * 64 + c2 + 1],       sacc[j][1]);
            atomicAdd(&g_S[(c1 + 8) * 64 + c2],     sacc[j][2]);
            atomicAdd(&g_S[(c1 + 8) * 64 + c2 + 1], sacc[j][3]);
        }
    }
}

// ---------------------------------------------------------------------------
// K_bn1 (moment trick, unchanged)
// ---------------------------------------------------------------------------
__global__ void k_bn1(const float* __restrict__ bfc, const float* __restrict__ g1,
                      const float* __restrict__ b1, float invCnt, float cnt) {
    __shared__ float sS[64 * 65];
    __shared__ float sw[64];
    __shared__ float red[4];
    int g = blockIdx.x;
    int i = threadIdx.x;
    sw[i] = g_Wfut[g * 64 + i];
    for (int l = i; l < 4096; l += 64)
        sS[(l >> 6) * 65 + (l & 63)] = g_S[l];
    __syncthreads();
    float y = 0.f;
    #pragma unroll 8
    for (int j = 0; j < 64; j++) y += sS[i * 65 + j] * sw[j];
    y *= sw[i];
    float p = sw[i] * g_svec[i];
    #pragma unroll
    for (int off = 16; off > 0; off >>= 1) {
        y += __shfl_xor_sync(0xffffffffu, y, off);
        p += __shfl_xor_sync(0xffffffffu, p, off);
    }
    if ((i & 31) == 0) { red[(i >> 5) * 2] = y; red[(i >> 5) * 2 + 1] = p; }
    __syncthreads();
    if (i == 0) {
        float quad = red[0] + red[2];
        float lin  = red[1] + red[3];
        float b    = bfc[g];
        float mean = lin * invCnt + b;
        float ex2  = (quad + 2.f * b * lin) * invCnt + b * b;
        float var  = ex2 - mean * mean;
        float sc   = g1[g] * rsqrtf(var + 1e-5f);
        g_sc1[g] = sc;
        g_sh1[g] = b1[g] - mean * sc;
    }
}

// ---------------------------------------------------------------------------
// K_gate: BD=256, occ 3. BN1 folded into weights/bias; MMA emits normalized
// values; sigmoid*softplus + sum over M -> g_s; BN2 stats.
// ---------------------------------------------------------------------------
#define GA_NF   0
#define GA_G    3264
#define SMEM_GATE_FLOATS 9600
#define SMEM_GATE_BYTES (SMEM_GATE_FLOATS * 4)

__global__ __launch_bounds__(GBD, 3) void k_gate(const float* __restrict__ bfc, int N) {
    extern __shared__ float sm[];
    float* sA = sm + GA_NF;
    float* sG = sm + GA_G;

    int tid  = threadIdx.x;
    int wid  = tid >> 5;          // 0..7
    int lane = tid & 31;
    int qid  = lane >> 2;
    int tq   = lane & 3;

    // BN1-folded B fragments + bias
    float bw[2][8][2];
    float bb[2][2];
    #pragma unroll
    for (int nti = 0; nti < 2; nti++) {
        int nt = 2 * wid + nti;
        float sc = g_sc1[nt * 8 + qid];
        #pragma unroll
        for (int ks = 0; ks < 8; ks++) {
            bw[nti][ks][0] = g_Wfut[(nt * 8 + qid) * 64 + ks * 8 + tq] * sc;
            bw[nti][ks][1] = g_Wfut[(nt * 8 + qid) * 64 + ks * 8 + tq + 4] * sc;
        }
        int gc0 = nt * 8 + 2 * tq;
        bb[nti][0] = bfc[gc0]     * g_sc1[gc0]     + g_sh1[gc0];
        bb[nti][1] = bfc[gc0 + 1] * g_sc1[gc0 + 1] + g_sh1[gc0 + 1];
    }
    int ga = tid >> 6, gc = tid & 63;
    float ls = 0.f, lq = 0.f;

    for (int grp = 0; grp < 8; grp++) {
        int n0 = blockIdx.x * APB + grp * 4;
        if (n0 >= N) break;

        const float* ai = g_att + (size_t)n0 * 768;
        #pragma unroll
        for (int s = 0; s < 12; s++) {
            int i = tid + s * GBD;
            sA[(i >> 6) * 68 + (i & 63)] = ai[i];
        }
        __syncthreads();

        #pragma unroll
        for (int mt = 0; mt < 3; mt++) {
            int r0 = 16 * mt + qid;
            float a[8][4];
            #pragma unroll
            for (int ks = 0; ks < 8; ks++) {
                int c0 = ks * 8 + tq;
                a[ks][0] = sA[r0 * 68 + c0];
                a[ks][1] = sA[(r0 + 8) * 68 + c0];
                a[ks][2] = sA[r0 * 68 + c0 + 4];
                a[ks][3] = sA[(r0 + 8) * 68 + c0 + 4];
            }
            #pragma unroll
            for (int nti = 0; nti < 2; nti++) {
                float d[4] = {0.f, 0.f, 0.f, 0.f};
                #pragma unroll
                for (int ks = 0; ks < 8; ks++)
                    mma8(d, a[ks][0], a[ks][1], a[ks][2], a[ks][3],
                         bw[nti][ks][0], bw[nti][ks][1]);
                int g0 = (2 * wid + nti) * 8 + 2 * tq;
                sG[r0 * 132 + g0]           = d[0] + bb[nti][0];
                sG[r0 * 132 + g0 + 1]       = d[1] + bb[nti][1];
                sG[(r0 + 8) * 132 + g0]     = d[2] + bb[nti][0];
                sG[(r0 + 8) * 132 + g0 + 1] = d[3] + bb[nti][1];
            }
        }
        __syncthreads();

        {
            float acc = 0.f;
            #pragma unroll
            for (int m = 0; m < MNBR; m++) {
                float f = sG[(ga * 12 + m) * 132 + gc];
                float h = sG[(ga * 12 + m) * 132 + 64 + gc];
                acc += sigf(f) * spf2(h);
            }
            g_s[(n0 + ga) * 64 + gc] = acc;
            ls += acc;
            lq += acc * acc;
        }
        __syncthreads();
    }
    atomicAdd(&g_sum2[gc], ls);
    atomicAdd(&g_sq2[gc],  lq);
}

// ---------------------------------------------------------------------------
__global__ void k_bn2(const float* __restrict__ g2, const float* __restrict__ b2, float invCnt) {
    int t = threadIdx.x;
    float m = g_sum2[t] * invCnt;
    float v = g_sq2[t] * invCnt - m * m;
    float sc = g2[t] * rsqrtf(v + 1e-5f);
    g_sc2[t] = sc;
    g_sh2[t] = b2[t] - m * sc;
}

__global__ void k_final(const float* __restrict__ atom, float* __restrict__ out, int total) {
    int i = blockIdx.x * blockDim.x + threadIdx.x;
    if (i >= total) return;
    int c = i & 63;
    float v = atom[i] + g_s[i] * g_sc2[c] + g_sh2[c];
    out[i] = spf2(v);
}

// ---------------------------------------------------------------------------
extern "C" void kernel_launch(void* const* d_in, const int* in_sizes, int n_in,
                              void* d_out, int out_size) {
    const float* atom = (const float*)d_in[0];
    const float* nbr  = (const float*)d_in[1];
    const int*   idx  = (const int*)  d_in[2];
    const float* WK   = (const float*)d_in[3];
    const float* WQ   = (const float*)d_in[4];
    const float* WV   = (const float*)d_in[5];
    const float* WO   = (const float*)d_in[6];
    const float* Wfc  = (const float*)d_in[7];
    const float* bfc  = (const float*)d_in[8];
    const float* bn1g = (const float*)d_in[9];
    const float* bn1b = (const float*)d_in[10];
    const float* bn2g = (const float*)d_in[11];
    const float* bn2b = (const float*)d_in[12];
    float* out = (float*)d_out;

    int N = in_sizes[0] / ATOMF;
    float cnt = (float)N * MNBR;

    cudaFuncSetAttribute(k_main, cudaFuncAttributeMaxDynamicSharedMemorySize, SMEM_MAIN_BYTES);
    cudaFuncSetAttribute(k_gate, cudaFuncAttributeMaxDynamicSharedMemorySize, SMEM_GATE_BYTES);

    k_prep<<<192, 256>>>(WK, WQ, WV, Wfc, WO);
    k_projT<<<(N + 47) / 48, 384>>>(atom, N);
    k_main<<<(N + APB - 1) / APB, BD, SMEM_MAIN_BYTES>>>(nbr, idx, N);
    k_bn1<<<128, 64>>>(bfc, bn1g, bn1b, 1.f / cnt, cnt);
    k_gate<<<(N + APB - 1) / APB, GBD, SMEM_GATE_BYTES>>>(bfc, N);
    k_bn2<<<1, 64>>>(bn2g, bn2b, 1.f / (float)N);
    k_final<<<(N * ATOMF + 255) / 256, 256>>>(atom, out, N * ATOMF);
}

// round 6
// speedup vs baseline: 2.1704x; 1.0508x over previous
#include <cuda_runtime.h>

// ---------------------------------------------------------------------------
#define NMAX   65536
#define MNBR   12
#define ATOMF  64
#define INF_   192
#define BD     384
#define GBD    256
#define APB    32      // atoms per block (8 groups of 4)

// ---------------------------------------------------------------------------
__device__ float g_Pself[NMAX * INF_];               // 48 MB
__device__ float g_Pnbr [NMAX * INF_];               // 48 MB
__device__ float g_att  [(size_t)NMAX * MNBR * 64];  // 201 MB (tf32-rounded)
__device__ float g_s    [NMAX * ATOMF];              // 16 MB
__device__ float g_WEt  [192 * 64];                  // edge weights, tf32
__device__ float g_Wall [384 * 64];                  // [self|nbr] proj weights, tf32
__device__ float g_Wfut [128 * 64];                  // fused W_fc@WO, tf32
__device__ float g_S    [64 * 64];
__device__ float g_svec [64];
__device__ float g_sum2[64], g_sq2[64];
__device__ float g_sc1[128], g_sh1[128], g_sc2[64], g_sh2[64];

// ---------------------------------------------------------------------------
__device__ __forceinline__ float tf32r(float x) {
    unsigned u; asm("cvt.rna.tf32.f32 %0, %1;" : "=r"(u) : "f"(x));
    return __uint_as_float(u);
}
__device__ __forceinline__ void mma8(float d[4], float a0, float a1, float a2, float a3,
                                     float b0, float b1) {
    unsigned A0 = __float_as_uint(a0), A1 = __float_as_uint(a1);
    unsigned A2 = __float_as_uint(a2), A3 = __float_as_uint(a3);
    unsigned B0 = __float_as_uint(b0), B1 = __float_as_uint(b1);
    asm volatile("mma.sync.aligned.m16n8k8.row.col.f32.tf32.tf32.f32 "
                 "{%0,%1,%2,%3}, {%4,%5,%6,%7}, {%8,%9}, {%0,%1,%2,%3};"
                 : "+f"(d[0]), "+f"(d[1]), "+f"(d[2]), "+f"(d[3])
                 : "r"(A0), "r"(A1), "r"(A2), "r"(A3), "r"(B0), "r"(B1));
}
__device__ __forceinline__ float sigf(float x) { return 1.f / (1.f + __expf(-x)); }
__device__ __forceinline__ float spf2(float x) {
    return fmaxf(x, 0.f) + __logf(1.f + __expf(-fabsf(x)));
}

__global__ void k_dummy(int x) { if (x == 12345) g_svec[63] += 0.f; }

// ---------------------------------------------------------------------------
// K_prep: tf32-round WEt, Wall; fuse W_fc@WO; zero stats. grid 192 x 256.
// ---------------------------------------------------------------------------
__global__ void k_prep(const float* __restrict__ WK, const float* __restrict__ WQ,
                       const float* __restrict__ WV, const float* __restrict__ Wfc,
                       const float* __restrict__ WO) {
    int t = threadIdx.x;
    if (blockIdx.x == 0 && t < 64) {
        g_sum2[t] = 0.f; g_sq2[t] = 0.f; g_svec[t] = 0.f;
    }
    int o = blockIdx.x * 256 + t;
    if (o < 12288) {
        int j = o >> 6, f = o & 63;
        const float* W = (j < 64) ? WK : ((j < 128) ? WQ : WV);
        g_WEt[o] = tf32r(W[(j & 63) * INF_ + 128 + f]);
    } else if (o < 36864) {
        int p = o - 12288;
        int j = p >> 6, f = p & 63;
        int half = (j >= 192);
        int jj = half ? j - 192 : j;
        const float* W = (jj < 64) ? WK : ((jj < 128) ? WQ : WV);
        g_Wall[p] = tf32r(W[(jj & 63) * INF_ + (half ? 64 : 0) + f]);
    } else if (o < 45056) {
        int p = o - 36864;
        int g = p >> 6, a = p & 63;
        const float* wr = Wfc + g * 256;
        float acc = 0.f;
        #pragma unroll 8
        for (int q = 0; q < 256; q++) acc += wr[q] * WO[q * 64 + a];
        g_Wfut[p] = tf32r(acc);
    } else if (o < 49152) {
        g_S[o - 45056] = 0.f;
    }
}

// ---------------------------------------------------------------------------
// K_projT (unchanged)
// ---------------------------------------------------------------------------
__global__ __launch_bounds__(384, 2) void k_projT(const float* __restrict__ atom, int N) {
    __shared__ float sAT[48 * 68];
    int tid = threadIdx.x, wid = tid >> 5, lane = tid & 31;
    int qid = lane >> 2, tq = lane & 3;
    int n0 = blockIdx.x * 48;

    #pragma unroll
    for (int s = 0; s < 8; s++) {
        int i = tid + s * 384;
        int r = i >> 6, c = i & 63;
        int n = n0 + r;
        float v = (n < N) ? atom[(size_t)n * 64 + c] : 0.f;
        sAT[r * 68 + c] = tf32r(v);
    }
    __syncthreads();

    #pragma unroll
    for (int half = 0; half < 2; half++) {
        const float* Wsrc = g_Wall + (half * 192 + wid * 16) * 64;
        float aw[8][4];
        #pragma unroll
        for (int ks = 0; ks < 8; ks++) {
            int f0 = ks * 8 + tq;
            aw[ks][0] = Wsrc[qid * 64 + f0];
            aw[ks][1] = Wsrc[(qid + 8) * 64 + f0];
            aw[ks][2] = Wsrc[qid * 64 + f0 + 4];
            aw[ks][3] = Wsrc[(qid + 8) * 64 + f0 + 4];
        }
        float* ob = half ? g_Pnbr : g_Pself;
        #pragma unroll
        for (int nt = 0; nt < 6; nt++) {
            float d[4] = {0.f, 0.f, 0.f, 0.f};
            const float* ar = sAT + (8 * nt + qid) * 68;
            #pragma unroll
            for (int ks = 0; ks < 8; ks++)
                mma8(d, aw[ks][0], aw[ks][1], aw[ks][2], aw[ks][3],
                     ar[ks * 8 + tq], ar[ks * 8 + tq + 4]);
            int r0  = 8 * nt + 2 * tq;
            int ch0 = wid * 16 + qid;
            if (n0 + r0 < N) {
                ob[(size_t)(n0 + r0) * INF_ + ch0]     = d[0];
                ob[(size_t)(n0 + r0) * INF_ + ch0 + 8] = d[2];
            }
            if (n0 + r0 + 1 < N) {
                ob[(size_t)(n0 + r0 + 1) * INF_ + ch0]     = d[1];
                ob[(size_t)(n0 + r0 + 1) * INF_ + ch0 + 8] = d[3];
            }
        }
    }
}

// ---------------------------------------------------------------------------
// K_main: 4 phases/group.
//   P1 load/gather | P2 edge MMA | P3 logits MMA + quad-shuffle softmax
//   P5 w@V MMA -> direct STG to g_att
// ---------------------------------------------------------------------------
#define O_NF   0
#define O_KQV  3264
#define O_LG   13664
#define SMEM_FLOATS 14752
#define SMEM_MAIN_BYTES (SMEM_FLOATS * 4)

__global__ __launch_bounds__(BD, 2) void k_main(const float* __restrict__ nbr,
                                                const int*   __restrict__ idx,
                                                int N) {
    extern __shared__ float sm[];
    float* sNF  = sm + O_NF;
    float* sKQV = sm + O_KQV;
    float* sLG  = sm + O_LG;

    int tid  = threadIdx.x;
    int wid  = tid >> 5;
    int lane = tid & 31;
    int qid  = lane >> 2;
    int tq   = lane & 3;

    float aw[8][4];
    {
        int ch0 = 16 * wid + qid;
        #pragma unroll
        for (int ks = 0; ks < 8; ks++) {
            int f0 = ks * 8 + tq;
            aw[ks][0] = g_WEt[ch0 * 64 + f0];
            aw[ks][1] = g_WEt[(ch0 + 8) * 64 + f0];
            aw[ks][2] = g_WEt[ch0 * 64 + f0 + 4];
            aw[ks][3] = g_WEt[(ch0 + 8) * 64 + f0 + 4];
        }
    }

    int hh = (tid >= 192) ? 1 : 0;
    int gch = tid - 192 * hh;

    // zero pad rows 48-51 of sKQV
    for (int i = tid; i < 4 * 200; i += BD) sKQV[48 * 200 + i] = 0.f;

    for (int grp = 0; grp < 8; grp++) {
        int n0 = blockIdx.x * APB + grp * 4;
        if (n0 >= N) break;

        // ---- P1: NF load + KQV gather ----
        {
            const float* nb = nbr + (size_t)n0 * 768;
            #pragma unroll
            for (int s = 0; s < 8; s++) {
                int i = tid + s * 384;
                sNF[(i >> 6) * 68 + (i & 63)] = tf32r(nb[i]);
            }
            float ps0 = g_Pself[(size_t)n0 * INF_ + gch];
            float ps1 = g_Pself[(size_t)(n0 + 1) * INF_ + gch];
            float ps2 = g_Pself[(size_t)(n0 + 2) * INF_ + gch];
            float ps3 = g_Pself[(size_t)(n0 + 3) * INF_ + gch];
            #pragma unroll
            for (int s = 0; s < 24; s++) {
                int e = 2 * s + hh;
                int j = idx[n0 * MNBR + e];
                float ps = (s < 6) ? ps0 : ((s < 12) ? ps1 : ((s < 18) ? ps2 : ps3));
                sKQV[e * 200 + gch] = ps + g_Pnbr[(size_t)j * INF_ + gch];
            }
        }
        __syncthreads();

        // ---- P2: edge MMA; epilogue rounds K/Q/V to tf32 ----
        {
            #pragma unroll
            for (int nt = 0; nt < 6; nt++) {
                float d[4] = {0.f, 0.f, 0.f, 0.f};
                const float* nrow = sNF + (8 * nt + qid) * 68;
                #pragma unroll
                for (int ks = 0; ks < 8; ks++) {
                    float b0 = nrow[ks * 8 + tq];
                    float b1 = nrow[ks * 8 + tq + 4];
                    mma8(d, aw[ks][0], aw[ks][1], aw[ks][2], aw[ks][3], b0, b1);
                }
                int e0  = 8 * nt + 2 * tq;
                int ch0 = 16 * wid + qid;
                sKQV[e0 * 200 + ch0]           = tf32r(sKQV[e0 * 200 + ch0] + d[0]);
                sKQV[(e0 + 1) * 200 + ch0]     = tf32r(sKQV[(e0 + 1) * 200 + ch0] + d[1]);
                sKQV[e0 * 200 + ch0 + 8]       = tf32r(sKQV[e0 * 200 + ch0 + 8] + d[2]);
                sKQV[(e0 + 1) * 200 + ch0 + 8] = tf32r(sKQV[(e0 + 1) * 200 + ch0 + 8] + d[3]);
            }
        }
        __syncthreads();

        // ---- P3: logits (warp per atom) + quad-shuffle softmax ----
        if (wid < 4) {
            int a  = wid;
            int r0 = 12 * a;
            float d0[4] = {0.f, 0.f, 0.f, 0.f};
            float d1[4] = {0.f, 0.f, 0.f, 0.f};
            #pragma unroll
            for (int s = 0; s < 8; s++) {
                int f = 8 * s + tq;
                float a0 = sKQV[(r0 + qid) * 200 + f];
                float a1 = sKQV[(r0 + qid + 8) * 200 + f];
                float a2 = sKQV[(r0 + qid) * 200 + f + 4];
                float a3 = sKQV[(r0 + qid + 8) * 200 + f + 4];
                float b00 = sKQV[(r0 + qid) * 200 + 64 + f];
                float b01 = sKQV[(r0 + qid) * 200 + 64 + f + 4];
                float b10 = sKQV[(r0 + 8 + qid) * 200 + 64 + f];
                float b11 = sKQV[(r0 + 8 + qid) * 200 + 64 + f + 4];
                mma8(d0, a0, a1, a2, a3, b00, b01);
                mma8(d1, a0, a1, a2, a3, b10, b11);
            }
            float* lg = sLG + a * 272;
            bool colBad = (tq >= 2);   // cols 12-15 invalid
            // --- row qid (always valid) ---
            {
                float l[4];
                l[0] = d0[0] * 0.125f; l[1] = d0[1] * 0.125f;
                l[2] = colBad ? -1e30f : d1[0] * 0.125f;
                l[3] = colBad ? -1e30f : d1[1] * 0.125f;
                float mx = fmaxf(fmaxf(l[0], l[1]), fmaxf(l[2], l[3]));
                mx = fmaxf(mx, __shfl_xor_sync(0xffffffffu, mx, 1));
                mx = fmaxf(mx, __shfl_xor_sync(0xffffffffu, mx, 2));
                float e0 = __expf(l[0] - mx), e1 = __expf(l[1] - mx);
                float e2 = __expf(l[2] - mx), e3 = __expf(l[3] - mx);
                float s = e0 + e1 + e2 + e3;
                s += __shfl_xor_sync(0xffffffffu, s, 1);
                s += __shfl_xor_sync(0xffffffffu, s, 2);
                float inv = 1.f / s;
                lg[qid * 17 + 2 * tq]         = tf32r(e0 * inv);
                lg[qid * 17 + 2 * tq + 1]     = tf32r(e1 * inv);
                lg[qid * 17 + 8 + 2 * tq]     = tf32r(e2 * inv);
                lg[qid * 17 + 8 + 2 * tq + 1] = tf32r(e3 * inv);
            }
            // --- row qid+8 (valid only for qid<4) ---
            {
                bool rowOk = (qid < 4);
                float l[4];
                l[0] = d0[2] * 0.125f; l[1] = d0[3] * 0.125f;
                l[2] = colBad ? -1e30f : d1[2] * 0.125f;
                l[3] = colBad ? -1e30f : d1[3] * 0.125f;
                float mx = fmaxf(fmaxf(l[0], l[1]), fmaxf(l[2], l[3]));
                mx = fmaxf(mx, __shfl_xor_sync(0xffffffffu, mx, 1));
                mx = fmaxf(mx, __shfl_xor_sync(0xffffffffu, mx, 2));
                float e0 = __expf(l[0] - mx), e1 = __expf(l[1] - mx);
                float e2 = __expf(l[2] - mx), e3 = __expf(l[3] - mx);
                float s = e0 + e1 + e2 + e3;
                s += __shfl_xor_sync(0xffffffffu, s, 1);
                s += __shfl_xor_sync(0xffffffffu, s, 2);
                float inv = rowOk ? (1.f / s) : 0.f;
                lg[(qid + 8) * 17 + 2 * tq]         = tf32r(e0 * inv);
                lg[(qid + 8) * 17 + 2 * tq + 1]     = tf32r(e1 * inv);
                lg[(qid + 8) * 17 + 8 + 2 * tq]     = tf32r(e2 * inv);
                lg[(qid + 8) * 17 + 8 + 2 * tq + 1] = tf32r(e3 * inv);
            }
        }
        __syncthreads();

        // ---- P5: attn = W @ V MMA -> direct STG to g_att ----
        if (wid < 8) {
            int a = wid >> 1;
            int ntb = (wid & 1) * 4;
            const float* lg = sLG + a * 272;
            float af[2][4];
            #pragma unroll
            for (int s = 0; s < 2; s++) {
                int k = 8 * s + tq;
                af[s][0] = lg[qid * 17 + k];
                af[s][1] = lg[(qid + 8) * 17 + k];
                af[s][2] = lg[qid * 17 + k + 4];
                af[s][3] = lg[(qid + 8) * 17 + k + 4];
            }
            float* go = g_att + (size_t)n0 * 768 + 12 * a * 64;
            #pragma unroll
            for (int j = 0; j < 4; j++) {
                int nt = ntb + j;
                float d[4] = {0.f, 0.f, 0.f, 0.f};
                #pragma unroll
                for (int s = 0; s < 2; s++) {
                    int kr = 12 * a + 8 * s + tq;
                    float b0 = sKQV[kr * 200 + 128 + 8 * nt + qid];
                    float b1 = sKQV[(kr + 4) * 200 + 128 + 8 * nt + qid];
                    mma8(d, af[s][0], af[s][1], af[s][2], af[s][3], b0, b1);
                }
                int col = 8 * nt + 2 * tq;
                float2 w0 = {tf32r(d[0]), tf32r(d[1])};
                *(float2*)&go[qid * 64 + col] = w0;
                if (qid < 4) {
                    float2 w1 = {tf32r(d[2]), tf32r(d[3])};
                    *(float2*)&go[(qid + 8) * 64 + col] = w1;
                }
            }
        }
        __syncthreads();   // sKQV reused next group
    }
}

// ---------------------------------------------------------------------------
// K_stats: S = att^T @ att (tf32 MMA) + svec, from g_att, 128-row chunks.
// ---------------------------------------------------------------------------
__global__ __launch_bounds__(256, 4) void k_stats(int nChunks) {
    __shared__ float sA[128 * 68];
    __shared__ float ssv[64];
    int tid  = threadIdx.x;
    int wid  = tid >> 5;
    int lane = tid & 31;
    int qid  = lane >> 2;
    int tq   = lane & 3;
    int mt   = wid >> 1;
    int ntb  = (wid & 1) * 4;

    if (tid < 64) ssv[tid] = 0.f;
    float sacc[4][4];
    #pragma unroll
    for (int i = 0; i < 4; i++)
        #pragma unroll
        for (int j = 0; j < 4; j++) sacc[i][j] = 0.f;
    float sv = 0.f;

    for (int ch = blockIdx.x; ch < nChunks; ch += gridDim.x) {
        const float* ai = g_att + (size_t)ch * 8192;
        __syncthreads();
        #pragma unroll
        for (int s = 0; s < 32; s++) {
            int i = tid + s * 256;
            float v = ai[i];
            sA[(i >> 6) * 68 + (i & 63)] = v;
            sv += v;
        }
        __syncthreads();
        #pragma unroll
        for (int ks = 0; ks < 16; ks++) {
            int kr = 8 * ks + tq;
            float a0 = sA[kr * 68 + 16 * mt + qid];
            float a1 = sA[kr * 68 + 16 * mt + qid + 8];
            float a2 = sA[(kr + 4) * 68 + 16 * mt + qid];
            float a3 = sA[(kr + 4) * 68 + 16 * mt + qid + 8];
            #pragma unroll
            for (int j = 0; j < 4; j++) {
                int nt = ntb + j;
                float b0 = sA[kr * 68 + 8 * nt + qid];
                float b1 = sA[(kr + 4) * 68 + 8 * nt + qid];
                mma8(sacc[j], a0, a1, a2, a3, b0, b1);
            }
        }
    }
    atomicAdd(&ssv[tid & 63], sv);
    #pragma unroll
    for (int j = 0; j < 4; j++) {
        int c1 = 16 * mt + qid;
        int c2 = 8 * (ntb + j) + 2 * tq;
        atomicAdd(&g_S[c1 * 64 + c2],           sacc[j][0]);
        atomicAdd(&g_S[c1 * 64 + c2 + 1],       sacc[j][1]);
        atomicAdd(&g_S[(c1 + 8) * 64 + c2],     sacc[j][2]);
        atomicAdd(&g_S[(c1 + 8) * 64 + c2 + 1], sacc[j][3]);
    }
    __syncthreads();
    if (tid < 64) atomicAdd(&g_svec[tid], ssv[tid]);
}

// ---------------------------------------------------------------------------
// K_bn1 (moment trick, unchanged)
// ---------------------------------------------------------------------------
__global__ void k_bn1(const float* __restrict__ bfc, const float* __restrict__ g1,
                      const float* __restrict__ b1, float invCnt, float cnt) {
    __shared__ float sS[64 * 65];
    __shared__ float sw[64];
    __shared__ float red[4];
    int g = blockIdx.x;
    int i = threadIdx.x;
    sw[i] = g_Wfut[g * 64 + i];
    for (int l = i; l < 4096; l += 64)
        sS[(l >> 6) * 65 + (l & 63)] = g_S[l];
    __syncthreads();
    float y = 0.f;
    #pragma unroll 8
    for (int j = 0; j < 64; j++) y += sS[i * 65 + j] * sw[j];
    y *= sw[i];
    float p = sw[i] * g_svec[i];
    #pragma unroll
    for (int off = 16; off > 0; off >>= 1) {
        y += __shfl_xor_sync(0xffffffffu, y, off);
        p += __shfl_xor_sync(0xffffffffu, p, off);
    }
    if ((i & 31) == 0) { red[(i >> 5) * 2] = y; red[(i >> 5) * 2 + 1] = p; }
    __syncthreads();
    if (i == 0) {
        float quad = red[0] + red[2];
        float lin  = red[1] + red[3];
        float b    = bfc[g];
        float mean = lin * invCnt + b;
        float ex2  = (quad + 2.f * b * lin) * invCnt + b * b;
        float var  = ex2 - mean * mean;
        float sc   = g1[g] * rsqrtf(var + 1e-5f);
        g_sc1[g] = sc;
        g_sh1[g] = b1[g] - mean * sc;
    }
}

// ---------------------------------------------------------------------------
// K_gate: register-resident gated + activation + per-atom reduction.
// Warp w handles filter cols 8w..8w+7 (nt=w) and core (nt=w+8).
// ---------------------------------------------------------------------------
#define SMEM_GATE_FLOATS (48 * 68)
#define SMEM_GATE_BYTES (SMEM_GATE_FLOATS * 4)

__global__ __launch_bounds__(GBD, 3) void k_gate(const float* __restrict__ bfc, int N) {
    extern __shared__ float sm[];
    float* sA = sm;

    int tid  = threadIdx.x;
    int wid  = tid >> 5;          // 0..7
    int lane = tid & 31;
    int qid  = lane >> 2;
    int tq   = lane & 3;

    // BN1-folded fragments: filter (nt=wid), core (nt=wid+8)
    float bwf[8][2], bwh[8][2];
    float bbf[2], bbh[2];
    {
        int rf = wid * 8 + qid;           // filter channel row
        int rh = 64 + wid * 8 + qid;      // core channel row
        float scf = g_sc1[rf], sch = g_sc1[rh];
        #pragma unroll
        for (int ks = 0; ks < 8; ks++) {
            bwf[ks][0] = tf32r(g_Wfut[rf * 64 + ks * 8 + tq] * scf);
            bwf[ks][1] = tf32r(g_Wfut[rf * 64 + ks * 8 + tq + 4] * scf);
            bwh[ks][0] = tf32r(g_Wfut[rh * 64 + ks * 8 + tq] * sch);
            bwh[ks][1] = tf32r(g_Wfut[rh * 64 + ks * 8 + tq + 4] * sch);
        }
        int cf = wid * 8 + 2 * tq;
        bbf[0] = bfc[cf]          * g_sc1[cf]          + g_sh1[cf];
        bbf[1] = bfc[cf + 1]      * g_sc1[cf + 1]      + g_sh1[cf + 1];
        bbh[0] = bfc[64 + cf]     * g_sc1[64 + cf]     + g_sh1[64 + cf];
        bbh[1] = bfc[64 + cf + 1] * g_sc1[64 + cf + 1] + g_sh1[64 + cf + 1];
    }
    float ls0 = 0.f, ls1 = 0.f, lq0 = 0.f, lq1 = 0.f;

    for (int grp = 0; grp < 8; grp++) {
        int n0 = blockIdx.x * APB + grp * 4;
        if (n0 >= N) break;

        const float* ai = g_att + (size_t)n0 * 768;
        #pragma unroll
        for (int s = 0; s < 12; s++) {
            int i = tid + s * GBD;
            sA[(i >> 6) * 68 + (i & 63)] = ai[i];
        }
        __syncthreads();

        float acc[4][2];
        #pragma unroll
        for (int a = 0; a < 4; a++) { acc[a][0] = 0.f; acc[a][1] = 0.f; }

        #pragma unroll
        for (int mt = 0; mt < 3; mt++) {
            int r0 = 16 * mt + qid;
            float a[8][4];
            #pragma unroll
            for (int ks = 0; ks < 8; ks++) {
                int c0 = ks * 8 + tq;
                a[ks][0] = sA[r0 * 68 + c0];
                a[ks][1] = sA[(r0 + 8) * 68 + c0];
                a[ks][2] = sA[r0 * 68 + c0 + 4];
                a[ks][3] = sA[(r0 + 8) * 68 + c0 + 4];
            }
            float f[4] = {0.f, 0.f, 0.f, 0.f};
            float h[4] = {0.f, 0.f, 0.f, 0.f};
            #pragma unroll
            for (int ks = 0; ks < 8; ks++) {
                mma8(f, a[ks][0], a[ks][1], a[ks][2], a[ks][3], bwf[ks][0], bwf[ks][1]);
                mma8(h, a[ks][0], a[ks][1], a[ks][2], a[ks][3], bwh[ks][0], bwh[ks][1]);
            }
            float v0 = sigf(f[0] + bbf[0]) * spf2(h[0] + bbh[0]);
            float v1 = sigf(f[1] + bbf[1]) * spf2(h[1] + bbh[1]);
            float v2 = sigf(f[2] + bbf[0]) * spf2(h[2] + bbh[0]);
            float v3 = sigf(f[3] + bbf[1]) * spf2(h[3] + bbh[1]);
            // rows: v0,v1 -> 16mt+qid ; v2,v3 -> 16mt+qid+8 ; atom = row/12
            if (mt == 0) {
                acc[0][0] += v0; acc[0][1] += v1;
                if (qid < 4) { acc[0][0] += v2; acc[0][1] += v3; }
                else         { acc[1][0] += v2; acc[1][1] += v3; }
            } else if (mt == 1) {
                acc[1][0] += v0; acc[1][1] += v1;
                acc[2][0] += v2; acc[2][1] += v3;
            } else {
                if (qid < 4) { acc[2][0] += v0; acc[2][1] += v1; }
                else         { acc[3][0] += v0; acc[3][1] += v1; }
                acc[3][0] += v2; acc[3][1] += v3;
            }
        }

        // reduce over qid (lanes differing in bits 2,3,4)
        #pragma unroll
        for (int a = 0; a < 4; a++) {
            #pragma unroll
            for (int c = 0; c < 2; c++) {
                float v = acc[a][c];
                v += __shfl_xor_sync(0xffffffffu, v, 4);
                v += __shfl_xor_sync(0xffffffffu, v, 8);
                v += __shfl_xor_sync(0xffffffffu, v, 16);
                acc[a][c] = v;
            }
        }
        if (lane < 4) {
            int col = wid * 8 + 2 * lane;
            #pragma unroll
            for (int a = 0; a < 4; a++) {
                g_s[(size_t)(n0 + a) * 64 + col]     = acc[a][0];
                g_s[(size_t)(n0 + a) * 64 + col + 1] = acc[a][1];
                ls0 += acc[a][0]; lq0 += acc[a][0] * acc[a][0];
                ls1 += acc[a][1]; lq1 += acc[a][1] * acc[a][1];
            }
        }
        __syncthreads();
    }
    if (lane < 4) {
        int col = wid * 8 + 2 * lane;
        atomicAdd(&g_sum2[col],     ls0);
        atomicAdd(&g_sq2[col],      lq0);
        atomicAdd(&g_sum2[col + 1], ls1);
        atomicAdd(&g_sq2[col + 1],  lq1);
    }
}

// ---------------------------------------------------------------------------
__global__ void k_bn2(const float* __restrict__ g2, const float* __restrict__ b2, float invCnt) {
    int t = threadIdx.x;
    float m = g_sum2[t] * invCnt;
    float v = g_sq2[t] * invCnt - m * m;
    float sc = g2[t] * rsqrtf(v + 1e-5f);
    g_sc2[t] = sc;
    g_sh2[t] = b2[t] - m * sc;
}

__global__ void k_final(const float* __restrict__ atom, float* __restrict__ out, int total) {
    int i = blockIdx.x * blockDim.x + threadIdx.x;
    if (i >= total) return;
    int c = i & 63;
    float v = atom[i] + g_s[i] * g_sc2[c] + g_sh2[c];
    out[i] = spf2(v);
}

// ---------------------------------------------------------------------------
extern "C" void kernel_launch(void* const* d_in, const int* in_sizes, int n_in,
                              void* d_out, int out_size) {
    const float* atom = (const float*)d_in[0];
    const float* nbr  = (const float*)d_in[1];
    const int*   idx  = (const int*)  d_in[2];
    const float* WK   = (const float*)d_in[3];
    const float* WQ   = (const float*)d_in[4];
    const float* WV   = (const float*)d_in[5];
    const float* WO   = (const float*)d_in[6];
    const float* Wfc  = (const float*)d_in[7];
    const float* bfc  = (const float*)d_in[8];
    const float* bn1g = (const float*)d_in[9];
    const float* bn1b = (const float*)d_in[10];
    const float* bn2g = (const float*)d_in[11];
    const float* bn2b = (const float*)d_in[12];
    float* out = (float*)d_out;

    int N = in_sizes[0] / ATOMF;
    float cnt = (float)N * MNBR;
    int nChunks = (N * MNBR * ATOMF) / 8192;

    cudaFuncSetAttribute(k_main, cudaFuncAttributeMaxDynamicSharedMemorySize, SMEM_MAIN_BYTES);
    cudaFuncSetAttribute(k_gate, cudaFuncAttributeMaxDynamicSharedMemorySize, SMEM_GATE_BYTES);

    k_prep<<<192, 256>>>(WK, WQ, WV, Wfc, WO);
    k_projT<<<(N + 47) / 48, 384>>>(atom, N);
    k_dummy<<<1, 32>>>(0);   // launch #3 -> k_main is the 4th launch (ncu -s lands on it)
    k_main<<<(N + APB - 1) / APB, BD, SMEM_MAIN_BYTES>>>(nbr, idx, N);
    k_stats<<<1024, 256>>>(nChunks);
    k_bn1<<<128, 64>>>(bfc, bn1g, bn1b, 1.f / cnt, cnt);
    k_gate<<<(N + APB - 1) / APB, GBD, SMEM_GATE_BYTES>>>(bfc, N);
    k_bn2<<<1, 64>>>(bn2g, bn2b, 1.f / (float)N);
    k_final<<<(N * ATOMF + 255) / 256, 256>>>(atom, out, N * ATOMF);
}

// round 7
// speedup vs baseline: 2.4997x; 1.1518x over previous
#include <cuda_runtime.h>

// ---------------------------------------------------------------------------
#define NMAX   65536
#define MNBR   12
#define ATOMF  64
#define INF_   192
#define BD     384
#define GBD    256
#define APB    32      // atoms per block (8 groups of 4)

// ---------------------------------------------------------------------------
__device__ float g_Pself[NMAX * INF_];               // 48 MB
__device__ float g_Pnbr [NMAX * INF_];               // 48 MB
__device__ float g_att  [(size_t)NMAX * MNBR * 64];  // 201 MB (tf32-rounded)
__device__ float g_s    [NMAX * ATOMF];              // 16 MB
__device__ float g_WEt  [192 * 64];                  // edge weights, tf32
__device__ float g_Wall [384 * 64];                  // [self|nbr] proj weights, tf32
__device__ float g_Wfut [128 * 64];                  // fused W_fc@WO, tf32
__device__ float g_S    [64 * 64];
__device__ float g_svec [64];
__device__ float g_sum2[64], g_sq2[64];
__device__ float g_sc1[128], g_sh1[128], g_sc2[64], g_sh2[64];

// ---------------------------------------------------------------------------
__device__ __forceinline__ float tf32r(float x) {
    unsigned u; asm("cvt.rna.tf32.f32 %0, %1;" : "=r"(u) : "f"(x));
    return __uint_as_float(u);
}
__device__ __forceinline__ void mma8(float d[4], float a0, float a1, float a2, float a3,
                                     float b0, float b1) {
    unsigned A0 = __float_as_uint(a0), A1 = __float_as_uint(a1);
    unsigned A2 = __float_as_uint(a2), A3 = __float_as_uint(a3);
    unsigned B0 = __float_as_uint(b0), B1 = __float_as_uint(b1);
    asm volatile("mma.sync.aligned.m16n8k8.row.col.f32.tf32.tf32.f32 "
                 "{%0,%1,%2,%3}, {%4,%5,%6,%7}, {%8,%9}, {%0,%1,%2,%3};"
                 : "+f"(d[0]), "+f"(d[1]), "+f"(d[2]), "+f"(d[3])
                 : "r"(A0), "r"(A1), "r"(A2), "r"(A3), "r"(B0), "r"(B1));
}
__device__ __forceinline__ float sigf(float x) { return 1.f / (1.f + __expf(-x)); }
__device__ __forceinline__ float spf2(float x) {
    return fmaxf(x, 0.f) + __logf(1.f + __expf(-fabsf(x)));
}

__global__ void k_dummy(int x) { if (x == 12345) g_svec[63] += 0.f; }

// ---------------------------------------------------------------------------
// K_prep: tf32-round WEt, Wall; fuse W_fc@WO; zero stats. grid 192 x 256.
// ---------------------------------------------------------------------------
__global__ void k_prep(const float* __restrict__ WK, const float* __restrict__ WQ,
                       const float* __restrict__ WV, const float* __restrict__ Wfc,
                       const float* __restrict__ WO) {
    int t = threadIdx.x;
    if (blockIdx.x == 0 && t < 64) {
        g_sum2[t] = 0.f; g_sq2[t] = 0.f; g_svec[t] = 0.f;
    }
    int o = blockIdx.x * 256 + t;
    if (o < 12288) {
        int j = o >> 6, f = o & 63;
        const float* W = (j < 64) ? WK : ((j < 128) ? WQ : WV);
        g_WEt[o] = tf32r(W[(j & 63) * INF_ + 128 + f]);
    } else if (o < 36864) {
        int p = o - 12288;
        int j = p >> 6, f = p & 63;
        int half = (j >= 192);
        int jj = half ? j - 192 : j;
        const float* W = (jj < 64) ? WK : ((jj < 128) ? WQ : WV);
        g_Wall[p] = tf32r(W[(jj & 63) * INF_ + (half ? 64 : 0) + f]);
    } else if (o < 45056) {
        int p = o - 36864;
        int g = p >> 6, a = p & 63;
        const float* wr = Wfc + g * 256;
        float acc = 0.f;
        #pragma unroll 8
        for (int q = 0; q < 256; q++) acc += wr[q] * WO[q * 64 + a];
        g_Wfut[p] = tf32r(acc);
    } else if (o < 49152) {
        g_S[o - 45056] = 0.f;
    }
}

// ---------------------------------------------------------------------------
// K_projT (unchanged)
// ---------------------------------------------------------------------------
__global__ __launch_bounds__(384, 2) void k_projT(const float* __restrict__ atom, int N) {
    __shared__ float sAT[48 * 68];
    int tid = threadIdx.x, wid = tid >> 5, lane = tid & 31;
    int qid = lane >> 2, tq = lane & 3;
    int n0 = blockIdx.x * 48;

    #pragma unroll
    for (int s = 0; s < 8; s++) {
        int i = tid + s * 384;
        int r = i >> 6, c = i & 63;
        int n = n0 + r;
        float v = (n < N) ? atom[(size_t)n * 64 + c] : 0.f;
        sAT[r * 68 + c] = tf32r(v);
    }
    __syncthreads();

    #pragma unroll
    for (int half = 0; half < 2; half++) {
        const float* Wsrc = g_Wall + (half * 192 + wid * 16) * 64;
        float aw[8][4];
        #pragma unroll
        for (int ks = 0; ks < 8; ks++) {
            int f0 = ks * 8 + tq;
            aw[ks][0] = Wsrc[qid * 64 + f0];
            aw[ks][1] = Wsrc[(qid + 8) * 64 + f0];
            aw[ks][2] = Wsrc[qid * 64 + f0 + 4];
            aw[ks][3] = Wsrc[(qid + 8) * 64 + f0 + 4];
        }
        float* ob = half ? g_Pnbr : g_Pself;
        #pragma unroll
        for (int nt = 0; nt < 6; nt++) {
            float d[4] = {0.f, 0.f, 0.f, 0.f};
            const float* ar = sAT + (8 * nt + qid) * 68;
            #pragma unroll
            for (int ks = 0; ks < 8; ks++)
                mma8(d, aw[ks][0], aw[ks][1], aw[ks][2], aw[ks][3],
                     ar[ks * 8 + tq], ar[ks * 8 + tq + 4]);
            int r0  = 8 * nt + 2 * tq;
            int ch0 = wid * 16 + qid;
            if (n0 + r0 < N) {
                ob[(size_t)(n0 + r0) * INF_ + ch0]     = d[0];
                ob[(size_t)(n0 + r0) * INF_ + ch0 + 8] = d[2];
            }
            if (n0 + r0 + 1 < N) {
                ob[(size_t)(n0 + r0 + 1) * INF_ + ch0]     = d[1];
                ob[(size_t)(n0 + r0 + 1) * INF_ + ch0 + 8] = d[3];
            }
        }
    }
}

// ---------------------------------------------------------------------------
// K_main: vectorized + double-buffered.
//   P1 vector gather (Pself+Pnbr -> sKQV) | P2 edge MMA (accumulate, tf32)
//   P3 logits+softmax (w0-3) / NF+idx prefetch (w4-11) | P5 w@V -> STG
// sKQV stride 204 (conflict-free epilogue + P5 loads, 16B-aligned)
// ---------------------------------------------------------------------------
#define O_NF    0                 // 2 x 48x68 = 6528
#define O_KQV   6528              // 52 x 204 = 10608
#define O_LG    17136             // 4 x 272  = 1088
#define O_J     18224             // 2 x 48 ints
#define SMEM_FLOATS 18320
#define SMEM_MAIN_BYTES (SMEM_FLOATS * 4)

__global__ __launch_bounds__(BD, 2) void k_main(const float* __restrict__ nbr,
                                                const int*   __restrict__ idx,
                                                int N) {
    extern __shared__ float sm[];
    float* sNF0 = sm + O_NF;
    float* sNF1 = sm + O_NF + 3264;
    float* sKQV = sm + O_KQV;
    float* sLG  = sm + O_LG;
    int*   sJ0  = (int*)(sm + O_J);
    int*   sJ1  = sJ0 + 48;

    int tid  = threadIdx.x;
    int wid  = tid >> 5;
    int lane = tid & 31;
    int qid  = lane >> 2;
    int tq   = lane & 3;

    float aw[8][4];
    {
        int ch0 = 16 * wid + qid;
        #pragma unroll
        for (int ks = 0; ks < 8; ks++) {
            int f0 = ks * 8 + tq;
            aw[ks][0] = g_WEt[ch0 * 64 + f0];
            aw[ks][1] = g_WEt[(ch0 + 8) * 64 + f0];
            aw[ks][2] = g_WEt[ch0 * 64 + f0 + 4];
            aw[ks][3] = g_WEt[(ch0 + 8) * 64 + f0 + 4];
        }
    }

    // zero pad rows 48-51 of sKQV
    for (int i = tid; i < 4 * 204; i += BD) sKQV[48 * 204 + i] = 0.f;

    // prologue: NF(0) + sJ(0)
    {
        int n00 = blockIdx.x * APB;
        const float4* nb4 = (const float4*)(nbr + (size_t)n00 * 768);
        #pragma unroll
        for (int s = 0; s < 2; s++) {
            int v = tid + s * 384;          // 768 float4
            float4 x = nb4[v];
            x.x = tf32r(x.x); x.y = tf32r(x.y); x.z = tf32r(x.z); x.w = tf32r(x.w);
            *(float4*)&sNF0[(v >> 4) * 68 + (v & 15) * 4] = x;
        }
        if (tid < 48) sJ0[tid] = idx[n00 * MNBR + tid];
    }
    __syncthreads();

    for (int grp = 0; grp < 8; grp++) {
        int n0 = blockIdx.x * APB + grp * 4;
        if (n0 >= N) break;
        float* sNF = (grp & 1) ? sNF1 : sNF0;
        int*   sJc = (grp & 1) ? sJ1  : sJ0;
        float* sNFn = (grp & 1) ? sNF0 : sNF1;
        int*   sJn  = (grp & 1) ? sJ0  : sJ1;

        // ---- P1: vector gather -> sKQV (f32) ----
        #pragma unroll
        for (int s = 0; s < 6; s++) {
            int v  = tid + s * 384;          // 2304 float4 = 48 edges x 48
            int e  = v / 48;
            int c4 = (v - e * 48) * 4;
            int j  = sJc[e];
            int at = e / 12;
            float4 pn = *(const float4*)&g_Pnbr [(size_t)j * INF_ + c4];
            float4 ps = *(const float4*)&g_Pself[(size_t)(n0 + at) * INF_ + c4];
            float4 r;
            r.x = pn.x + ps.x; r.y = pn.y + ps.y;
            r.z = pn.z + ps.z; r.w = pn.w + ps.w;
            *(float4*)&sKQV[e * 204 + c4] = r;
        }
        __syncthreads();

        // ---- P2: edge MMA accumulating gather; epilogue tf32 ----
        {
            int ch0 = 16 * wid + qid;
            #pragma unroll
            for (int nt = 0; nt < 6; nt++) {
                int e0 = 8 * nt + 2 * tq;
                float d[4];
                d[0] = sKQV[e0 * 204 + ch0];
                d[1] = sKQV[(e0 + 1) * 204 + ch0];
                d[2] = sKQV[e0 * 204 + ch0 + 8];
                d[3] = sKQV[(e0 + 1) * 204 + ch0 + 8];
                const float* nrow = sNF + (8 * nt + qid) * 68;
                #pragma unroll
                for (int ks = 0; ks < 8; ks++) {
                    float b0 = nrow[ks * 8 + tq];
                    float b1 = nrow[ks * 8 + tq + 4];
                    mma8(d, aw[ks][0], aw[ks][1], aw[ks][2], aw[ks][3], b0, b1);
                }
                sKQV[e0 * 204 + ch0]           = tf32r(d[0]);
                sKQV[(e0 + 1) * 204 + ch0]     = tf32r(d[1]);
                sKQV[e0 * 204 + ch0 + 8]       = tf32r(d[2]);
                sKQV[(e0 + 1) * 204 + ch0 + 8] = tf32r(d[3]);
            }
        }
        __syncthreads();

        // ---- P3: logits+softmax (warps 0-3) | NF/idx prefetch (warps 4-11) ----
        if (wid < 4) {
            int a  = wid;
            int r0 = 12 * a;
            float d0[4] = {0.f, 0.f, 0.f, 0.f};
            float d1[4] = {0.f, 0.f, 0.f, 0.f};
            #pragma unroll
            for (int s = 0; s < 8; s++) {
                int f = 8 * s + tq;
                float a0 = sKQV[(r0 + qid) * 204 + f];
                float a1 = sKQV[(r0 + qid + 8) * 204 + f];
                float a2 = sKQV[(r0 + qid) * 204 + f + 4];
                float a3 = sKQV[(r0 + qid + 8) * 204 + f + 4];
                float b00 = sKQV[(r0 + qid) * 204 + 64 + f];
                float b01 = sKQV[(r0 + qid) * 204 + 64 + f + 4];
                float b10 = sKQV[(r0 + 8 + qid) * 204 + 64 + f];
                float b11 = sKQV[(r0 + 8 + qid) * 204 + 64 + f + 4];
                mma8(d0, a0, a1, a2, a3, b00, b01);
                mma8(d1, a0, a1, a2, a3, b10, b11);
            }
            float* lg = sLG + a * 272;
            bool colBad = (tq >= 2);
            {
                float l[4];
                l[0] = d0[0] * 0.125f; l[1] = d0[1] * 0.125f;
                l[2] = colBad ? -1e30f : d1[0] * 0.125f;
                l[3] = colBad ? -1e30f : d1[1] * 0.125f;
                float mx = fmaxf(fmaxf(l[0], l[1]), fmaxf(l[2], l[3]));
                mx = fmaxf(mx, __shfl_xor_sync(0xffffffffu, mx, 1));
                mx = fmaxf(mx, __shfl_xor_sync(0xffffffffu, mx, 2));
                float e0 = __expf(l[0] - mx), e1 = __expf(l[1] - mx);
                float e2 = __expf(l[2] - mx), e3 = __expf(l[3] - mx);
                float s = e0 + e1 + e2 + e3;
                s += __shfl_xor_sync(0xffffffffu, s, 1);
                s += __shfl_xor_sync(0xffffffffu, s, 2);
                float inv = 1.f / s;
                lg[qid * 17 + 2 * tq]         = tf32r(e0 * inv);
                lg[qid * 17 + 2 * tq + 1]     = tf32r(e1 * inv);
                lg[qid * 17 + 8 + 2 * tq]     = tf32r(e2 * inv);
                lg[qid * 17 + 8 + 2 * tq + 1] = tf32r(e3 * inv);
            }
            {
                bool rowOk = (qid < 4);
                float l[4];
                l[0] = d0[2] * 0.125f; l[1] = d0[3] * 0.125f;
                l[2] = colBad ? -1e30f : d1[2] * 0.125f;
                l[3] = colBad ? -1e30f : d1[3] * 0.125f;
                float mx = fmaxf(fmaxf(l[0], l[1]), fmaxf(l[2], l[3]));
                mx = fmaxf(mx, __shfl_xor_sync(0xffffffffu, mx, 1));
                mx = fmaxf(mx, __shfl_xor_sync(0xffffffffu, mx, 2));
                float e0 = __expf(l[0] - mx), e1 = __expf(l[1] - mx);
                float e2 = __expf(l[2] - mx), e3 = __expf(l[3] - mx);
                float s = e0 + e1 + e2 + e3;
                s += __shfl_xor_sync(0xffffffffu, s, 1);
                s += __shfl_xor_sync(0xffffffffu, s, 2);
                float inv = rowOk ? (1.f / s) : 0.f;
                lg[(qid + 8) * 17 + 2 * tq]         = tf32r(e0 * inv);
                lg[(qid + 8) * 17 + 2 * tq + 1]     = tf32r(e1 * inv);
                lg[(qid + 8) * 17 + 8 + 2 * tq]     = tf32r(e2 * inv);
                lg[(qid + 8) * 17 + 8 + 2 * tq + 1] = tf32r(e3 * inv);
            }
        } else if (grp < 7) {
            int n1 = n0 + 4;
            if (n1 < N) {
                int t2 = tid - 128;            // 0..255
                const float4* nb4 = (const float4*)(nbr + (size_t)n1 * 768);
                #pragma unroll
                for (int s = 0; s < 3; s++) {
                    int v = t2 + s * 256;      // 768 float4
                    float4 x = nb4[v];
                    x.x = tf32r(x.x); x.y = tf32r(x.y); x.z = tf32r(x.z); x.w = tf32r(x.w);
                    *(float4*)&sNFn[(v >> 4) * 68 + (v & 15) * 4] = x;
                }
                if (t2 < 48) sJn[t2] = idx[n1 * MNBR + t2];
            }
        }
        __syncthreads();

        // ---- P5: attn = W @ V MMA -> direct STG to g_att ----
        if (wid < 8) {
            int a = wid >> 1;
            int ntb = (wid & 1) * 4;
            const float* lg = sLG + a * 272;
            float af[2][4];
            #pragma unroll
            for (int s = 0; s < 2; s++) {
                int k = 8 * s + tq;
                af[s][0] = lg[qid * 17 + k];
                af[s][1] = lg[(qid + 8) * 17 + k];
                af[s][2] = lg[qid * 17 + k + 4];
                af[s][3] = lg[(qid + 8) * 17 + k + 4];
            }
            float* go = g_att + (size_t)n0 * 768 + 12 * a * 64;
            #pragma unroll
            for (int j = 0; j < 4; j++) {
                int nt = ntb + j;
                float d[4] = {0.f, 0.f, 0.f, 0.f};
                #pragma unroll
                for (int s = 0; s < 2; s++) {
                    int kr = 12 * a + 8 * s + tq;
                    float b0 = sKQV[kr * 204 + 128 + 8 * nt + qid];
                    float b1 = sKQV[(kr + 4) * 204 + 128 + 8 * nt + qid];
                    mma8(d, af[s][0], af[s][1], af[s][2], af[s][3], b0, b1);
                }
                int col = 8 * nt + 2 * tq;
                float2 w0 = {tf32r(d[0]), tf32r(d[1])};
                *(float2*)&go[qid * 64 + col] = w0;
                if (qid < 4) {
                    float2 w1 = {tf32r(d[2]), tf32r(d[3])};
                    *(float2*)&go[(qid + 8) * 64 + col] = w1;
                }
            }
        }
        __syncthreads();   // sKQV reused next group
    }
}

// ---------------------------------------------------------------------------
// K_stats: S = att^T @ att + svec, vectorized loads.
// ---------------------------------------------------------------------------
__global__ __launch_bounds__(256, 4) void k_stats(int nChunks) {
    __shared__ float sA[128 * 68];
    __shared__ float ssv[64];
    int tid  = threadIdx.x;
    int wid  = tid >> 5;
    int lane = tid & 31;
    int qid  = lane >> 2;
    int tq   = lane & 3;
    int mt   = wid >> 1;
    int ntb  = (wid & 1) * 4;

    if (tid < 64) ssv[tid] = 0.f;
    float sacc[4][4];
    #pragma unroll
    for (int i = 0; i < 4; i++)
        #pragma unroll
        for (int j = 0; j < 4; j++) sacc[i][j] = 0.f;
    float sv = 0.f;

    for (int ch = blockIdx.x; ch < nChunks; ch += gridDim.x) {
        const float4* ai4 = (const float4*)(g_att + (size_t)ch * 8192);
        __syncthreads();
        #pragma unroll
        for (int s = 0; s < 8; s++) {
            int v = tid + s * 256;           // 2048 float4
            float4 x = ai4[v];
            *(float4*)&sA[(v >> 4) * 68 + (v & 15) * 4] = x;
            sv += x.x + x.y + x.z + x.w;
        }
        __syncthreads();
        #pragma unroll
        for (int ks = 0; ks < 16; ks++) {
            int kr = 8 * ks + tq;
            float a0 = sA[kr * 68 + 16 * mt + qid];
            float a1 = sA[kr * 68 + 16 * mt + qid + 8];
            float a2 = sA[(kr + 4) * 68 + 16 * mt + qid];
            float a3 = sA[(kr + 4) * 68 + 16 * mt + qid + 8];
            #pragma unroll
            for (int j = 0; j < 4; j++) {
                int nt = ntb + j;
                float b0 = sA[kr * 68 + 8 * nt + qid];
                float b1 = sA[(kr + 4) * 68 + 8 * nt + qid];
                mma8(sacc[j], a0, a1, a2, a3, b0, b1);
            }
        }
    }
    atomicAdd(&ssv[tid & 63], sv);
    #pragma unroll
    for (int j = 0; j < 4; j++) {
        int c1 = 16 * mt + qid;
        int c2 = 8 * (ntb + j) + 2 * tq;
        atomicAdd(&g_S[c1 * 64 + c2],           sacc[j][0]);
        atomicAdd(&g_S[c1 * 64 + c2 + 1],       sacc[j][1]);
        atomicAdd(&g_S[(c1 + 8) * 64 + c2],     sacc[j][2]);
        atomicAdd(&g_S[(c1 + 8) * 64 + c2 + 1], sacc[j][3]);
    }
    __syncthreads();
    if (tid < 64) atomicAdd(&g_svec[tid], ssv[tid]);
}

// ---------------------------------------------------------------------------
// K_bn1 (moment trick, unchanged)
// ---------------------------------------------------------------------------
__global__ void k_bn1(const float* __restrict__ bfc, const float* __restrict__ g1,
                      const float* __restrict__ b1, float invCnt, float cnt) {
    __shared__ float sS[64 * 65];
    __shared__ float sw[64];
    __shared__ float red[4];
    int g = blockIdx.x;
    int i = threadIdx.x;
    sw[i] = g_Wfut[g * 64 + i];
    for (int l = i; l < 4096; l += 64)
        sS[(l >> 6) * 65 + (l & 63)] = g_S[l];
    __syncthreads();
    float y = 0.f;
    #pragma unroll 8
    for (int j = 0; j < 64; j++) y += sS[i * 65 + j] * sw[j];
    y *= sw[i];
    float p = sw[i] * g_svec[i];
    #pragma unroll
    for (int off = 16; off > 0; off >>= 1) {
        y += __shfl_xor_sync(0xffffffffu, y, off);
        p += __shfl_xor_sync(0xffffffffu, p, off);
    }
    if ((i & 31) == 0) { red[(i >> 5) * 2] = y; red[(i >> 5) * 2 + 1] = p; }
    __syncthreads();
    if (i == 0) {
        float quad = red[0] + red[2];
        float lin  = red[1] + red[3];
        float b    = bfc[g];
        float mean = lin * invCnt + b;
        float ex2  = (quad + 2.f * b * lin) * invCnt + b * b;
        float var  = ex2 - mean * mean;
        float sc   = g1[g] * rsqrtf(var + 1e-5f);
        g_sc1[g] = sc;
        g_sh1[g] = b1[g] - mean * sc;
    }
}

// ---------------------------------------------------------------------------
// K_gate: register-resident gated + activation + per-atom reduction.
// ---------------------------------------------------------------------------
#define SMEM_GATE_FLOATS (48 * 68)
#define SMEM_GATE_BYTES (SMEM_GATE_FLOATS * 4)

__global__ __launch_bounds__(GBD, 3) void k_gate(const float* __restrict__ bfc, int N) {
    extern __shared__ float sm[];
    float* sA = sm;

    int tid  = threadIdx.x;
    int wid  = tid >> 5;
    int lane = tid & 31;
    int qid  = lane >> 2;
    int tq   = lane & 3;

    float bwf[8][2], bwh[8][2];
    float bbf[2], bbh[2];
    {
        int rf = wid * 8 + qid;
        int rh = 64 + wid * 8 + qid;
        float scf = g_sc1[rf], sch = g_sc1[rh];
        #pragma unroll
        for (int ks = 0; ks < 8; ks++) {
            bwf[ks][0] = tf32r(g_Wfut[rf * 64 + ks * 8 + tq] * scf);
            bwf[ks][1] = tf32r(g_Wfut[rf * 64 + ks * 8 + tq + 4] * scf);
            bwh[ks][0] = tf32r(g_Wfut[rh * 64 + ks * 8 + tq] * sch);
            bwh[ks][1] = tf32r(g_Wfut[rh * 64 + ks * 8 + tq + 4] * sch);
        }
        int cf = wid * 8 + 2 * tq;
        bbf[0] = bfc[cf]          * g_sc1[cf]          + g_sh1[cf];
        bbf[1] = bfc[cf + 1]      * g_sc1[cf + 1]      + g_sh1[cf + 1];
        bbh[0] = bfc[64 + cf]     * g_sc1[64 + cf]     + g_sh1[64 + cf];
        bbh[1] = bfc[64 + cf + 1] * g_sc1[64 + cf + 1] + g_sh1[64 + cf + 1];
    }
    float ls0 = 0.f, ls1 = 0.f, lq0 = 0.f, lq1 = 0.f;

    for (int grp = 0; grp < 8; grp++) {
        int n0 = blockIdx.x * APB + grp * 4;
        if (n0 >= N) break;

        const float4* ai4 = (const float4*)(g_att + (size_t)n0 * 768);
        #pragma unroll
        for (int s = 0; s < 3; s++) {
            int v = tid + s * GBD;           // 768 float4
            float4 x = ai4[v];
            *(float4*)&sA[(v >> 4) * 68 + (v & 15) * 4] = x;
        }
        __syncthreads();

        float acc[4][2];
        #pragma unroll
        for (int a = 0; a < 4; a++) { acc[a][0] = 0.f; acc[a][1] = 0.f; }

        #pragma unroll
        for (int mt = 0; mt < 3; mt++) {
            int r0 = 16 * mt + qid;
            float a[8][4];
            #pragma unroll
            for (int ks = 0; ks < 8; ks++) {
                int c0 = ks * 8 + tq;
                a[ks][0] = sA[r0 * 68 + c0];
                a[ks][1] = sA[(r0 + 8) * 68 + c0];
                a[ks][2] = sA[r0 * 68 + c0 + 4];
                a[ks][3] = sA[(r0 + 8) * 68 + c0 + 4];
            }
            float f[4] = {0.f, 0.f, 0.f, 0.f};
            float h[4] = {0.f, 0.f, 0.f, 0.f};
            #pragma unroll
            for (int ks = 0; ks < 8; ks++) {
                mma8(f, a[ks][0], a[ks][1], a[ks][2], a[ks][3], bwf[ks][0], bwf[ks][1]);
                mma8(h, a[ks][0], a[ks][1], a[ks][2], a[ks][3], bwh[ks][0], bwh[ks][1]);
            }
            float v0 = sigf(f[0] + bbf[0]) * spf2(h[0] + bbh[0]);
            float v1 = sigf(f[1] + bbf[1]) * spf2(h[1] + bbh[1]);
            float v2 = sigf(f[2] + bbf[0]) * spf2(h[2] + bbh[0]);
            float v3 = sigf(f[3] + bbf[1]) * spf2(h[3] + bbh[1]);
            if (mt == 0) {
                acc[0][0] += v0; acc[0][1] += v1;
                if (qid < 4) { acc[0][0] += v2; acc[0][1] += v3; }
                else         { acc[1][0] += v2; acc[1][1] += v3; }
            } else if (mt == 1) {
                acc[1][0] += v0; acc[1][1] += v1;
                acc[2][0] += v2; acc[2][1] += v3;
            } else {
                if (qid < 4) { acc[2][0] += v0; acc[2][1] += v1; }
                else         { acc[3][0] += v0; acc[3][1] += v1; }
                acc[3][0] += v2; acc[3][1] += v3;
            }
        }

        #pragma unroll
        for (int a = 0; a < 4; a++) {
            #pragma unroll
            for (int c = 0; c < 2; c++) {
                float v = acc[a][c];
                v += __shfl_xor_sync(0xffffffffu, v, 4);
                v += __shfl_xor_sync(0xffffffffu, v, 8);
                v += __shfl_xor_sync(0xffffffffu, v, 16);
                acc[a][c] = v;
            }
        }
        if (lane < 4) {
            int col = wid * 8 + 2 * lane;
            #pragma unroll
            for (int a = 0; a < 4; a++) {
                g_s[(size_t)(n0 + a) * 64 + col]     = acc[a][0];
                g_s[(size_t)(n0 + a) * 64 + col + 1] = acc[a][1];
                ls0 += acc[a][0]; lq0 += acc[a][0] * acc[a][0];
                ls1 += acc[a][1]; lq1 += acc[a][1] * acc[a][1];
            }
        }
        __syncthreads();
    }
    if (lane < 4) {
        int col = wid * 8 + 2 * lane;
        atomicAdd(&g_sum2[col],     ls0);
        atomicAdd(&g_sq2[col],      lq0);
        atomicAdd(&g_sum2[col + 1], ls1);
        atomicAdd(&g_sq2[col + 1],  lq1);
    }
}

// ---------------------------------------------------------------------------
__global__ void k_bn2(const float* __restrict__ g2, const float* __restrict__ b2, float invCnt) {
    int t = threadIdx.x;
    float m = g_sum2[t] * invCnt;
    float v = g_sq2[t] * invCnt - m * m;
    float sc = g2[t] * rsqrtf(v + 1e-5f);
    g_sc2[t] = sc;
    g_sh2[t] = b2[t] - m * sc;
}

__global__ void k_final(const float* __restrict__ atom, float* __restrict__ out, int nVec) {
    int i = blockIdx.x * blockDim.x + threadIdx.x;
    if (i >= nVec) return;
    int c4 = (i & 15) * 4;
    float4 a = *(const float4*)&atom[(size_t)i * 4];
    float4 s = *(const float4*)&g_s[(size_t)i * 4];
    float4 o;
    o.x = spf2(a.x + s.x * g_sc2[c4]     + g_sh2[c4]);
    o.y = spf2(a.y + s.y * g_sc2[c4 + 1] + g_sh2[c4 + 1]);
    o.z = spf2(a.z + s.z * g_sc2[c4 + 2] + g_sh2[c4 + 2]);
    o.w = spf2(a.w + s.w * g_sc2[c4 + 3] + g_sh2[c4 + 3]);
    *(float4*)&out[(size_t)i * 4] = o;
}

// ---------------------------------------------------------------------------
extern "C" void kernel_launch(void* const* d_in, const int* in_sizes, int n_in,
                              void* d_out, int out_size) {
    const float* atom = (const float*)d_in[0];
    const float* nbr  = (const float*)d_in[1];
    const int*   idx  = (const int*)  d_in[2];
    const float* WK   = (const float*)d_in[3];
    const float* WQ   = (const float*)d_in[4];
    const float* WV   = (const float*)d_in[5];
    const float* WO   = (const float*)d_in[6];
    const float* Wfc  = (const float*)d_in[7];
    const float* bfc  = (const float*)d_in[8];
    const float* bn1g = (const float*)d_in[9];
    const float* bn1b = (const float*)d_in[10];
    const float* bn2g = (const float*)d_in[11];
    const float* bn2b = (const float*)d_in[12];
    float* out = (float*)d_out;

    int N = in_sizes[0] / ATOMF;
    float cnt = (float)N * MNBR;
    int nChunks = (N * MNBR * ATOMF) / 8192;

    cudaFuncSetAttribute(k_main, cudaFuncAttributeMaxDynamicSharedMemorySize, SMEM_MAIN_BYTES);
    cudaFuncSetAttribute(k_gate, cudaFuncAttributeMaxDynamicSharedMemorySize, SMEM_GATE_BYTES);

    k_prep<<<192, 256>>>(WK, WQ, WV, Wfc, WO);
    k_projT<<<(N + 47) / 48, 384>>>(atom, N);
    k_dummy<<<1, 32>>>(0);   // keep k_main as the 4th launch for ncu
    k_main<<<(N + APB - 1) / APB, BD, SMEM_MAIN_BYTES>>>(nbr, idx, N);
    k_stats<<<1024, 256>>>(nChunks);
    k_bn1<<<128, 64>>>(bfc, bn1g, bn1b, 1.f / cnt, cnt);
    k_gate<<<(N + APB - 1) / APB, GBD, SMEM_GATE_BYTES>>>(bfc, N);
    k_bn2<<<1, 64>>>(bn2g, bn2b, 1.f / (float)N);
    k_final<<<(N * ATOMF / 4 + 255) / 256, 256>>>(atom, out, N * ATOMF / 4);
}